// round 12
// baseline (speedup 1.0000x reference)
#include <cuda_runtime.h>
#include <cuda_fp16.h>
#include <cstdint>

#define N_NODES_MAX 100000
#define DIM         64
#define MAX_TILES   128      // scan tiles of 1024 -> supports n <= 131072

// ---- scratch (allocation-free rule: __device__ globals) ----
__device__ __align__(256) __half g_y16[N_NODES_MAX * DIM]; // fp16 (feature*norm)@W^T
__device__ __align__(16) int g_count[N_NODES_MAX];         // per-dst degree
__device__ __align__(16) int g_offset[N_NODES_MAX];        // ABSOLUTE offsets / cursors
__device__ int g_sorted_src[2000000];                      // src grouped by dst
__device__ int g_tilesums[MAX_TILES];                      // raw per-tile sums
__device__ unsigned g_bar_ctr = 0;                         // grid barrier (monotonic)

// ---------------------------------------------------------------------------
// Software grid barrier: generation counter, wrap-safe, deterministic across
// graph replays (counter only ever increments; no reset needed).
// REQUIRES all blocks co-resident (grid sized via occupancy API).
// ---------------------------------------------------------------------------
__device__ __forceinline__ void grid_barrier(unsigned G) {
    __syncthreads();
    if (threadIdx.x == 0) {
        __threadfence();
        unsigned t = atomicAdd(&g_bar_ctr, 1u);
        unsigned base = (t / G) * G;
        for (;;) {
            unsigned c;
            asm volatile("ld.acquire.gpu.global.u32 %0, [%1];"
                         : "=r"(c) : "l"(&g_bar_ctr));
            if (c - base >= G) break;
            __nanosleep(64);
        }
    }
    __syncthreads();
}

__device__ __forceinline__ void acc_h16(float4& a, uint2 v) {
    float2 lo = __half22float2(*reinterpret_cast<__half2*>(&v.x));
    float2 hi = __half22float2(*reinterpret_cast<__half2*>(&v.y));
    a.x += lo.x; a.y += lo.y; a.z += hi.x; a.w += hi.y;
}
__device__ __forceinline__ uint2 h2add(uint2 a, uint2 b) {
    uint2 r;
    asm("add.rn.f16x2 %0, %1, %2;" : "=r"(r.x) : "r"(a.x), "r"(b.x));
    asm("add.rn.f16x2 %0, %1, %2;" : "=r"(r.y) : "r"(a.y), "r"(b.y));
    return r;
}

// ---------------------------------------------------------------------------
// THE fused kernel: transform+hist | scan | fill | gather, one launch.
// ---------------------------------------------------------------------------
__global__ void __launch_bounds__(256, 6)
fused_kernel(const float* __restrict__ feature,
             const float* __restrict__ norm,
             const float* __restrict__ W,
             const int* __restrict__ src,
             const int* __restrict__ dst,
             const float* __restrict__ bias,
             float* __restrict__ out,
             int n, int e, unsigned G) {
    __shared__ float Wt[DIM * DIM];     // Wt[i*64+j] = W[j*64+i]
    __shared__ int s_sums[MAX_TILES];   // scanned tile sums (exclusive)
    __shared__ int s_warp[8];

    int tid = threadIdx.x;
    int bid = blockIdx.x;
    int lane = tid & 31, wid = tid >> 5;

    // ================= Phase A: Wt stage + histogram + transform ===========
    for (int k = tid; k < DIM * DIM; k += 256) {
        int j = k >> 6, i = k & 63;
        Wt[i * DIM + j] = W[k];
    }
    for (int i = bid * 256 + tid; i < e; i += (int)G * 256)
        atomicAdd(&g_count[__ldg(dst + i)], 1);
    __syncthreads();

    int ntiles64 = (n + 63) >> 6;
    for (int tile = bid; tile < ntiles64; tile += (int)G) {
        int node = tile * 64 + (tid >> 2);
        int jg   = (tid & 3) * 16;
        if (node >= n) continue;
        float nv = __ldg(norm + node);

        unsigned long long a01, a23, a45, a67, a89, aab, acd, aef;
        asm("mov.b64 %0, {%1, %1};" : "=l"(a01) : "f"(0.0f));
        a23 = a01; a45 = a01; a67 = a01; a89 = a01; aab = a01; acd = a01; aef = a01;

        const float4* arow = reinterpret_cast<const float4*>(feature + (size_t)node * DIM);
#pragma unroll
        for (int i4 = 0; i4 < 16; i4++) {
            float4 a = arow[i4];
            a.x *= nv; a.y *= nv; a.z *= nv; a.w *= nv;
            const float av[4] = {a.x, a.y, a.z, a.w};
#pragma unroll
            for (int c = 0; c < 4; c++) {
                int i = i4 * 4 + c;
                unsigned long long aa;
                asm("mov.b64 %0, {%1, %1};" : "=l"(aa) : "f"(av[c]));
                const ulonglong2* wp = reinterpret_cast<const ulonglong2*>(&Wt[i * DIM + jg]);
                ulonglong2 w0 = wp[0], w1 = wp[1];
                asm("fma.rn.f32x2 %0, %1, %2, %0;" : "+l"(a01) : "l"(aa), "l"(w0.x));
                asm("fma.rn.f32x2 %0, %1, %2, %0;" : "+l"(a23) : "l"(aa), "l"(w0.y));
                asm("fma.rn.f32x2 %0, %1, %2, %0;" : "+l"(a45) : "l"(aa), "l"(w1.x));
                asm("fma.rn.f32x2 %0, %1, %2, %0;" : "+l"(a67) : "l"(aa), "l"(w1.y));
                const ulonglong2* wq = reinterpret_cast<const ulonglong2*>(&Wt[i * DIM + jg + 8]);
                ulonglong2 w2 = wq[0], w3 = wq[1];
                asm("fma.rn.f32x2 %0, %1, %2, %0;" : "+l"(a89) : "l"(aa), "l"(w2.x));
                asm("fma.rn.f32x2 %0, %1, %2, %0;" : "+l"(aab) : "l"(aa), "l"(w2.y));
                asm("fma.rn.f32x2 %0, %1, %2, %0;" : "+l"(acd) : "l"(aa), "l"(w3.x));
                asm("fma.rn.f32x2 %0, %1, %2, %0;" : "+l"(aef) : "l"(aa), "l"(w3.y));
            }
        }

        float r[16];
        asm("mov.b64 {%0, %1}, %2;" : "=f"(r[0]), "=f"(r[1]) : "l"(a01));
        asm("mov.b64 {%0, %1}, %2;" : "=f"(r[2]), "=f"(r[3]) : "l"(a23));
        asm("mov.b64 {%0, %1}, %2;" : "=f"(r[4]), "=f"(r[5]) : "l"(a45));
        asm("mov.b64 {%0, %1}, %2;" : "=f"(r[6]), "=f"(r[7]) : "l"(a67));
        asm("mov.b64 {%0, %1}, %2;" : "=f"(r[8]), "=f"(r[9]) : "l"(a89));
        asm("mov.b64 {%0, %1}, %2;" : "=f"(r[10]), "=f"(r[11]) : "l"(aab));
        asm("mov.b64 {%0, %1}, %2;" : "=f"(r[12]), "=f"(r[13]) : "l"(acd));
        asm("mov.b64 {%0, %1}, %2;" : "=f"(r[14]), "=f"(r[15]) : "l"(aef));

        uint4 p0, p1;
        __half2 h;
        h = __floats2half2_rn(r[0],  r[1]);  p0.x = *reinterpret_cast<uint32_t*>(&h);
        h = __floats2half2_rn(r[2],  r[3]);  p0.y = *reinterpret_cast<uint32_t*>(&h);
        h = __floats2half2_rn(r[4],  r[5]);  p0.z = *reinterpret_cast<uint32_t*>(&h);
        h = __floats2half2_rn(r[6],  r[7]);  p0.w = *reinterpret_cast<uint32_t*>(&h);
        h = __floats2half2_rn(r[8],  r[9]);  p1.x = *reinterpret_cast<uint32_t*>(&h);
        h = __floats2half2_rn(r[10], r[11]); p1.y = *reinterpret_cast<uint32_t*>(&h);
        h = __floats2half2_rn(r[12], r[13]); p1.z = *reinterpret_cast<uint32_t*>(&h);
        h = __floats2half2_rn(r[14], r[15]); p1.w = *reinterpret_cast<uint32_t*>(&h);
        uint4* yp = reinterpret_cast<uint4*>(g_y16 + (size_t)node * DIM + jg);
        yp[0] = p0;
        yp[1] = p1;
    }

    grid_barrier(G);

    // ================= Phase B1: raw tile sums (tiles of 1024) =============
    int nst = (n + 1023) >> 10;
    for (int t = bid; t < nst; t += (int)G) {
        int base = t * 1024 + tid * 4;
        int s = 0;
        if (base + 3 < n) {
            int4 v = *reinterpret_cast<const int4*>(g_count + base);
            s = v.x + v.y + v.z + v.w;
        } else {
            for (int j = 0; j < 4 && base + j < n; j++) s += g_count[base + j];
        }
#pragma unroll
        for (int d = 16; d > 0; d >>= 1)
            s += __shfl_xor_sync(0xffffffffu, s, d);
        if (lane == 0) s_warp[wid] = s;
        __syncthreads();
        if (tid == 0) {
            int tot = 0;
#pragma unroll
            for (int j = 0; j < 8; j++) tot += s_warp[j];
            g_tilesums[t] = tot;
        }
        __syncthreads();
    }

    grid_barrier(G);

    // ===== Phase B2: every block scans tile sums (redundant) + own tiles ====
    {
        int v0 = 0;
        if (tid < MAX_TILES) {
            v0 = (tid < nst) ? g_tilesums[tid] : 0;
            s_sums[tid] = v0;
        }
        __syncthreads();
#pragma unroll
        for (int d = 1; d < MAX_TILES; d <<= 1) {
            int t = (tid < MAX_TILES && tid >= d) ? s_sums[tid - d] : 0;
            __syncthreads();
            if (tid < MAX_TILES) s_sums[tid] += t;
            __syncthreads();
        }
        if (tid < MAX_TILES) s_sums[tid] -= v0;   // exclusive
        __syncthreads();
    }
    for (int t = bid; t < nst; t += (int)G) {
        int tile_base = s_sums[t];
        int base = t * 1024 + tid * 4;
        int4 v = make_int4(0, 0, 0, 0);
        if (base + 3 < n) {
            v = *reinterpret_cast<const int4*>(g_count + base);
        } else {
            if (base + 0 < n) v.x = g_count[base + 0];
            if (base + 1 < n) v.y = g_count[base + 1];
            if (base + 2 < n) v.z = g_count[base + 2];
            if (base + 3 < n) v.w = g_count[base + 3];
        }
        int s1 = v.x + v.y, s2 = s1 + v.z, s3 = s2 + v.w;
        int tsum = s3;
        int p = tsum;
#pragma unroll
        for (int d = 1; d < 32; d <<= 1) {
            int t2 = __shfl_up_sync(0xffffffffu, p, d);
            if (lane >= d) p += t2;
        }
        if (lane == 31) s_warp[wid] = p;
        __syncthreads();
        if (wid == 0 && lane < 8) {
            int w = s_warp[lane];
            int q = w;
#pragma unroll
            for (int d = 1; d < 8; d <<= 1) {
                int t2 = __shfl_up_sync(0xffu, q, d);
                if (lane >= d) q += t2;
            }
            s_warp[lane] = q - w;
        }
        __syncthreads();
        int excl = tile_base + s_warp[wid] + (p - tsum);
        if (base + 0 < n) g_offset[base + 0] = excl;
        if (base + 1 < n) g_offset[base + 1] = excl + v.x;
        if (base + 2 < n) g_offset[base + 2] = excl + s1;
        if (base + 3 < n) g_offset[base + 3] = excl + s2;
        __syncthreads();
    }

    grid_barrier(G);

    // ================= Phase C: fill (absolute cursors) =====================
    int nq = (e + 3) >> 2;
    for (int q = bid * 256 + tid; q < nq; q += (int)G * 256) {
        int i = q * 4;
        if (i + 4 <= e) {
            int4 d4 = __ldg(reinterpret_cast<const int4*>(dst + i));
            int4 s4 = __ldg(reinterpret_cast<const int4*>(src + i));
            int p0 = atomicAdd(&g_offset[d4.x], 1);
            int p1 = atomicAdd(&g_offset[d4.y], 1);
            int p2 = atomicAdd(&g_offset[d4.z], 1);
            int p3 = atomicAdd(&g_offset[d4.w], 1);
            g_sorted_src[p0] = s4.x;
            g_sorted_src[p1] = s4.y;
            g_sorted_src[p2] = s4.z;
            g_sorted_src[p3] = s4.w;
        } else {
            for (; i < e; i++) {
                int d = __ldg(dst + i);
                int p = atomicAdd(&g_offset[d], 1);
                g_sorted_src[p] = __ldg(src + i);
            }
        }
    }

    grid_barrier(G);

    // ================= Phase D: gather + epilogue ===========================
    // After fill, g_offset[node] == absolute END of node's edge range.
    int half = lane >> 4;
    int c16  = lane & 15;
    const uint2* __restrict__ y2 = reinterpret_cast<const uint2*>(g_y16);
    int nwarp_nodes = n;
    for (int node = bid * 8 + wid; node < nwarp_nodes; node += (int)G * 8) {
        int deg = __ldg(g_count + node);
        int end = __ldg(g_offset + node);
        int k   = end - deg;

        float4 acc0 = make_float4(0.f, 0.f, 0.f, 0.f);
        float4 acc1 = make_float4(0.f, 0.f, 0.f, 0.f);

        for (; k + 8 <= end; k += 8) {
            int s0 = __ldg(g_sorted_src + k + 0 + half);
            int s1 = __ldg(g_sorted_src + k + 2 + half);
            int s2 = __ldg(g_sorted_src + k + 4 + half);
            int s3 = __ldg(g_sorted_src + k + 6 + half);
            uint2 v0 = __ldg(y2 + (size_t)s0 * 16 + c16);
            uint2 v1 = __ldg(y2 + (size_t)s1 * 16 + c16);
            uint2 v2 = __ldg(y2 + (size_t)s2 * 16 + c16);
            uint2 v3 = __ldg(y2 + (size_t)s3 * 16 + c16);
            acc_h16(acc0, h2add(h2add(v0, v1), h2add(v2, v3)));
        }
        if (k + 4 <= end) {
            int s0 = __ldg(g_sorted_src + k + 0 + half);
            int s1 = __ldg(g_sorted_src + k + 2 + half);
            uint2 v0 = __ldg(y2 + (size_t)s0 * 16 + c16);
            uint2 v1 = __ldg(y2 + (size_t)s1 * 16 + c16);
            acc_h16(acc1, h2add(v0, v1));
            k += 4;
        }
        if (k + 2 <= end) {
            int s = __ldg(g_sorted_src + k + half);
            uint2 v = __ldg(y2 + (size_t)s * 16 + c16);
            acc_h16(acc0, v);
            k += 2;
        }
        if (k < end && half == 0) {
            int s = __ldg(g_sorted_src + k);
            uint2 v = __ldg(y2 + (size_t)s * 16 + c16);
            acc_h16(acc1, v);
        }

        acc0.x += acc1.x; acc0.y += acc1.y; acc0.z += acc1.z; acc0.w += acc1.w;

        acc0.x += __shfl_xor_sync(0xffffffffu, acc0.x, 16);
        acc0.y += __shfl_xor_sync(0xffffffffu, acc0.y, 16);
        acc0.z += __shfl_xor_sync(0xffffffffu, acc0.z, 16);
        acc0.w += __shfl_xor_sync(0xffffffffu, acc0.w, 16);

        if (half == 0) {
            float nv = __ldg(norm + node);
            float4 bv = reinterpret_cast<const float4*>(bias)[c16];
            acc0.x = fmaf(acc0.x, nv, bv.x);
            acc0.y = fmaf(acc0.y, nv, bv.y);
            acc0.z = fmaf(acc0.z, nv, bv.z);
            acc0.w = fmaf(acc0.w, nv, bv.w);
            reinterpret_cast<float4*>(out + (size_t)node * DIM)[c16] = acc0;
        }
    }
}

// ---------------------------------------------------------------------------
// Launch. Inputs: 0 feature [N,64] f32, 1 norm [N] f32, 2 src [E] i32,
//                 3 dst [E] i32, 4 W [64,64] f32, 5 b [64] f32. out [N,64] f32.
// ---------------------------------------------------------------------------
extern "C" void kernel_launch(void* const* d_in, const int* in_sizes, int n_in,
                              void* d_out, int out_size) {
    const float* feature = (const float*)d_in[0];
    const float* norm    = (const float*)d_in[1];
    const int*   src     = (const int*)d_in[2];
    const int*   dst     = (const int*)d_in[3];
    const float* W       = (const float*)d_in[4];
    const float* b       = (const float*)d_in[5];
    float*       out     = (float*)d_out;

    int n = in_sizes[1];
    int e = in_sizes[2];

    void* count_ptr = nullptr;
    cudaGetSymbolAddress(&count_ptr, g_count);
    cudaMemsetAsync(count_ptr, 0, (size_t)n * sizeof(int));

    // Grid sized for guaranteed co-residency (software grid barrier safety).
    int dev = 0, sms = 148, maxb = 0;
    cudaGetDevice(&dev);
    cudaDeviceGetAttribute(&sms, cudaDevAttrMultiProcessorCount, dev);
    cudaOccupancyMaxActiveBlocksPerMultiprocessor(&maxb, fused_kernel, 256, 0);
    if (maxb < 1) maxb = 1;
    unsigned G = (unsigned)(sms * maxb);

    fused_kernel<<<G, 256>>>(feature, norm, W, src, dst, b, out, n, e, G);
}

// round 13
// speedup vs baseline: 1.0527x; 1.0527x over previous
#include <cuda_runtime.h>
#include <cuda_fp16.h>
#include <cstdint>

#define N_NODES_MAX 100000
#define DIM         64
#define MAX_TILES   128      // scan tiles of 1024 -> supports n <= 131072

// ---- scratch (allocation-free rule: __device__ globals) ----
__device__ __align__(256) __half g_y16[N_NODES_MAX * DIM]; // fp16 (feature*norm)@W^T
__device__ __align__(16) int g_count[N_NODES_MAX];         // per-dst degree
__device__ __align__(16) int g_offset[N_NODES_MAX];        // ABSOLUTE offsets / cursors
__device__ int g_sorted_src[2000000];                      // src grouped by dst
__device__ int g_tilesums[MAX_TILES];                      // raw per-tile sums
__device__ unsigned g_bar_ctr = 0;                         // grid barrier (monotonic)

// ---------------------------------------------------------------------------
// Software grid barrier: generation counter, wrap-safe, deterministic across
// graph replays (counter only ever increments; no reset needed).
// REQUIRES all blocks co-resident (grid sized via occupancy API).
// ---------------------------------------------------------------------------
__device__ __forceinline__ void grid_barrier(unsigned G) {
    __syncthreads();
    if (threadIdx.x == 0) {
        __threadfence();
        unsigned t = atomicAdd(&g_bar_ctr, 1u);
        unsigned base = (t / G) * G;
        for (;;) {
            unsigned c;
            asm volatile("ld.acquire.gpu.global.u32 %0, [%1];"
                         : "=r"(c) : "l"(&g_bar_ctr));
            if (c - base >= G) break;
            __nanosleep(64);
        }
    }
    __syncthreads();
}

__device__ __forceinline__ void acc_h16(float4& a, uint2 v) {
    float2 lo = __half22float2(*reinterpret_cast<__half2*>(&v.x));
    float2 hi = __half22float2(*reinterpret_cast<__half2*>(&v.y));
    a.x += lo.x; a.y += lo.y; a.z += hi.x; a.w += hi.y;
}
__device__ __forceinline__ uint2 h2add(uint2 a, uint2 b) {
    uint2 r;
    asm("add.rn.f16x2 %0, %1, %2;" : "=r"(r.x) : "r"(a.x), "r"(b.x));
    asm("add.rn.f16x2 %0, %1, %2;" : "=r"(r.y) : "r"(a.y), "r"(b.y));
    return r;
}

// ---------------------------------------------------------------------------
// THE fused kernel: transform+hist | scan | fill | gather, one launch.
// __launch_bounds__(256, 4): 64-reg budget -> NO SPILLS in the GEMM phase
// (the (256,6)/40-reg version spilled to local and saturated L1 at 68%).
// ---------------------------------------------------------------------------
__global__ void __launch_bounds__(256, 4)
fused_kernel(const float* __restrict__ feature,
             const float* __restrict__ norm,
             const float* __restrict__ W,
             const int* __restrict__ src,
             const int* __restrict__ dst,
             const float* __restrict__ bias,
             float* __restrict__ out,
             int n, int e, unsigned G) {
    __shared__ float Wt[DIM * DIM];     // Wt[i*64+j] = W[j*64+i]
    __shared__ int s_sums[MAX_TILES];   // scanned tile sums (exclusive)
    __shared__ int s_warp[8];

    int tid = threadIdx.x;
    int bid = blockIdx.x;
    int lane = tid & 31, wid = tid >> 5;

    // ================= Phase A: Wt stage + histogram + transform ===========
    for (int k = tid; k < DIM * DIM; k += 256) {
        int j = k >> 6, i = k & 63;
        Wt[i * DIM + j] = W[k];
    }
    for (int i = bid * 256 + tid; i < e; i += (int)G * 256)
        atomicAdd(&g_count[__ldg(dst + i)], 1);
    __syncthreads();

    int ntiles64 = (n + 63) >> 6;
    for (int tile = bid; tile < ntiles64; tile += (int)G) {
        int node = tile * 64 + (tid >> 2);
        int jg   = (tid & 3) * 16;
        if (node >= n) continue;
        float nv = __ldg(norm + node);

        unsigned long long a01, a23, a45, a67, a89, aab, acd, aef;
        asm("mov.b64 %0, {%1, %1};" : "=l"(a01) : "f"(0.0f));
        a23 = a01; a45 = a01; a67 = a01; a89 = a01; aab = a01; acd = a01; aef = a01;

        const float4* arow = reinterpret_cast<const float4*>(feature + (size_t)node * DIM);
#pragma unroll
        for (int i4 = 0; i4 < 16; i4++) {
            float4 a = arow[i4];
            a.x *= nv; a.y *= nv; a.z *= nv; a.w *= nv;
            const float av[4] = {a.x, a.y, a.z, a.w};
#pragma unroll
            for (int c = 0; c < 4; c++) {
                int i = i4 * 4 + c;
                unsigned long long aa;
                asm("mov.b64 %0, {%1, %1};" : "=l"(aa) : "f"(av[c]));
                const ulonglong2* wp = reinterpret_cast<const ulonglong2*>(&Wt[i * DIM + jg]);
                ulonglong2 w0 = wp[0], w1 = wp[1];
                asm("fma.rn.f32x2 %0, %1, %2, %0;" : "+l"(a01) : "l"(aa), "l"(w0.x));
                asm("fma.rn.f32x2 %0, %1, %2, %0;" : "+l"(a23) : "l"(aa), "l"(w0.y));
                asm("fma.rn.f32x2 %0, %1, %2, %0;" : "+l"(a45) : "l"(aa), "l"(w1.x));
                asm("fma.rn.f32x2 %0, %1, %2, %0;" : "+l"(a67) : "l"(aa), "l"(w1.y));
                const ulonglong2* wq = reinterpret_cast<const ulonglong2*>(&Wt[i * DIM + jg + 8]);
                ulonglong2 w2 = wq[0], w3 = wq[1];
                asm("fma.rn.f32x2 %0, %1, %2, %0;" : "+l"(a89) : "l"(aa), "l"(w2.x));
                asm("fma.rn.f32x2 %0, %1, %2, %0;" : "+l"(aab) : "l"(aa), "l"(w2.y));
                asm("fma.rn.f32x2 %0, %1, %2, %0;" : "+l"(acd) : "l"(aa), "l"(w3.x));
                asm("fma.rn.f32x2 %0, %1, %2, %0;" : "+l"(aef) : "l"(aa), "l"(w3.y));
            }
        }

        float r[16];
        asm("mov.b64 {%0, %1}, %2;" : "=f"(r[0]), "=f"(r[1]) : "l"(a01));
        asm("mov.b64 {%0, %1}, %2;" : "=f"(r[2]), "=f"(r[3]) : "l"(a23));
        asm("mov.b64 {%0, %1}, %2;" : "=f"(r[4]), "=f"(r[5]) : "l"(a45));
        asm("mov.b64 {%0, %1}, %2;" : "=f"(r[6]), "=f"(r[7]) : "l"(a67));
        asm("mov.b64 {%0, %1}, %2;" : "=f"(r[8]), "=f"(r[9]) : "l"(a89));
        asm("mov.b64 {%0, %1}, %2;" : "=f"(r[10]), "=f"(r[11]) : "l"(aab));
        asm("mov.b64 {%0, %1}, %2;" : "=f"(r[12]), "=f"(r[13]) : "l"(acd));
        asm("mov.b64 {%0, %1}, %2;" : "=f"(r[14]), "=f"(r[15]) : "l"(aef));

        uint4 p0, p1;
        __half2 h;
        h = __floats2half2_rn(r[0],  r[1]);  p0.x = *reinterpret_cast<uint32_t*>(&h);
        h = __floats2half2_rn(r[2],  r[3]);  p0.y = *reinterpret_cast<uint32_t*>(&h);
        h = __floats2half2_rn(r[4],  r[5]);  p0.z = *reinterpret_cast<uint32_t*>(&h);
        h = __floats2half2_rn(r[6],  r[7]);  p0.w = *reinterpret_cast<uint32_t*>(&h);
        h = __floats2half2_rn(r[8],  r[9]);  p1.x = *reinterpret_cast<uint32_t*>(&h);
        h = __floats2half2_rn(r[10], r[11]); p1.y = *reinterpret_cast<uint32_t*>(&h);
        h = __floats2half2_rn(r[12], r[13]); p1.z = *reinterpret_cast<uint32_t*>(&h);
        h = __floats2half2_rn(r[14], r[15]); p1.w = *reinterpret_cast<uint32_t*>(&h);
        uint4* yp = reinterpret_cast<uint4*>(g_y16 + (size_t)node * DIM + jg);
        yp[0] = p0;
        yp[1] = p1;
    }

    grid_barrier(G);

    // ================= Phase B1: raw tile sums (tiles of 1024) =============
    int nst = (n + 1023) >> 10;
    for (int t = bid; t < nst; t += (int)G) {
        int base = t * 1024 + tid * 4;
        int s = 0;
        if (base + 3 < n) {
            int4 v = *reinterpret_cast<const int4*>(g_count + base);
            s = v.x + v.y + v.z + v.w;
        } else {
            for (int j = 0; j < 4 && base + j < n; j++) s += g_count[base + j];
        }
#pragma unroll
        for (int d = 16; d > 0; d >>= 1)
            s += __shfl_xor_sync(0xffffffffu, s, d);
        if (lane == 0) s_warp[wid] = s;
        __syncthreads();
        if (tid == 0) {
            int tot = 0;
#pragma unroll
            for (int j = 0; j < 8; j++) tot += s_warp[j];
            g_tilesums[t] = tot;
        }
        __syncthreads();
    }

    grid_barrier(G);

    // ===== Phase B2: every block scans tile sums (redundant) + own tiles ====
    {
        int v0 = 0;
        if (tid < MAX_TILES) {
            v0 = (tid < nst) ? g_tilesums[tid] : 0;
            s_sums[tid] = v0;
        }
        __syncthreads();
#pragma unroll
        for (int d = 1; d < MAX_TILES; d <<= 1) {
            int t = (tid < MAX_TILES && tid >= d) ? s_sums[tid - d] : 0;
            __syncthreads();
            if (tid < MAX_TILES) s_sums[tid] += t;
            __syncthreads();
        }
        if (tid < MAX_TILES) s_sums[tid] -= v0;   // exclusive
        __syncthreads();
    }
    for (int t = bid; t < nst; t += (int)G) {
        int tile_base = s_sums[t];
        int base = t * 1024 + tid * 4;
        int4 v = make_int4(0, 0, 0, 0);
        if (base + 3 < n) {
            v = *reinterpret_cast<const int4*>(g_count + base);
        } else {
            if (base + 0 < n) v.x = g_count[base + 0];
            if (base + 1 < n) v.y = g_count[base + 1];
            if (base + 2 < n) v.z = g_count[base + 2];
            if (base + 3 < n) v.w = g_count[base + 3];
        }
        int s1 = v.x + v.y, s2 = s1 + v.z, s3 = s2 + v.w;
        int tsum = s3;
        int p = tsum;
#pragma unroll
        for (int d = 1; d < 32; d <<= 1) {
            int t2 = __shfl_up_sync(0xffffffffu, p, d);
            if (lane >= d) p += t2;
        }
        if (lane == 31) s_warp[wid] = p;
        __syncthreads();
        if (wid == 0 && lane < 8) {
            int w = s_warp[lane];
            int q = w;
#pragma unroll
            for (int d = 1; d < 8; d <<= 1) {
                int t2 = __shfl_up_sync(0xffu, q, d);
                if (lane >= d) q += t2;
            }
            s_warp[lane] = q - w;
        }
        __syncthreads();
        int excl = tile_base + s_warp[wid] + (p - tsum);
        if (base + 0 < n) g_offset[base + 0] = excl;
        if (base + 1 < n) g_offset[base + 1] = excl + v.x;
        if (base + 2 < n) g_offset[base + 2] = excl + s1;
        if (base + 3 < n) g_offset[base + 3] = excl + s2;
        __syncthreads();
    }

    grid_barrier(G);

    // ================= Phase C: fill (absolute cursors) =====================
    int nq = (e + 3) >> 2;
    for (int q = bid * 256 + tid; q < nq; q += (int)G * 256) {
        int i = q * 4;
        if (i + 4 <= e) {
            int4 d4 = __ldg(reinterpret_cast<const int4*>(dst + i));
            int4 s4 = __ldg(reinterpret_cast<const int4*>(src + i));
            int p0 = atomicAdd(&g_offset[d4.x], 1);
            int p1 = atomicAdd(&g_offset[d4.y], 1);
            int p2 = atomicAdd(&g_offset[d4.z], 1);
            int p3 = atomicAdd(&g_offset[d4.w], 1);
            g_sorted_src[p0] = s4.x;
            g_sorted_src[p1] = s4.y;
            g_sorted_src[p2] = s4.z;
            g_sorted_src[p3] = s4.w;
        } else {
            for (; i < e; i++) {
                int d = __ldg(dst + i);
                int p = atomicAdd(&g_offset[d], 1);
                g_sorted_src[p] = __ldg(src + i);
            }
        }
    }

    grid_barrier(G);

    // ================= Phase D: gather + epilogue ===========================
    // After fill, g_offset[node] == absolute END of node's edge range.
    int half = lane >> 4;
    int c16  = lane & 15;
    const uint2* __restrict__ y2 = reinterpret_cast<const uint2*>(g_y16);
    for (int node = bid * 8 + wid; node < n; node += (int)G * 8) {
        int deg = __ldg(g_count + node);
        int end = __ldg(g_offset + node);
        int k   = end - deg;

        float4 acc0 = make_float4(0.f, 0.f, 0.f, 0.f);
        float4 acc1 = make_float4(0.f, 0.f, 0.f, 0.f);

        for (; k + 8 <= end; k += 8) {
            int s0 = __ldg(g_sorted_src + k + 0 + half);
            int s1 = __ldg(g_sorted_src + k + 2 + half);
            int s2 = __ldg(g_sorted_src + k + 4 + half);
            int s3 = __ldg(g_sorted_src + k + 6 + half);
            uint2 v0 = __ldg(y2 + (size_t)s0 * 16 + c16);
            uint2 v1 = __ldg(y2 + (size_t)s1 * 16 + c16);
            uint2 v2 = __ldg(y2 + (size_t)s2 * 16 + c16);
            uint2 v3 = __ldg(y2 + (size_t)s3 * 16 + c16);
            acc_h16(acc0, h2add(h2add(v0, v1), h2add(v2, v3)));
        }
        if (k + 4 <= end) {
            int s0 = __ldg(g_sorted_src + k + 0 + half);
            int s1 = __ldg(g_sorted_src + k + 2 + half);
            uint2 v0 = __ldg(y2 + (size_t)s0 * 16 + c16);
            uint2 v1 = __ldg(y2 + (size_t)s1 * 16 + c16);
            acc_h16(acc1, h2add(v0, v1));
            k += 4;
        }
        if (k + 2 <= end) {
            int s = __ldg(g_sorted_src + k + half);
            uint2 v = __ldg(y2 + (size_t)s * 16 + c16);
            acc_h16(acc0, v);
            k += 2;
        }
        if (k < end && half == 0) {
            int s = __ldg(g_sorted_src + k);
            uint2 v = __ldg(y2 + (size_t)s * 16 + c16);
            acc_h16(acc1, v);
        }

        acc0.x += acc1.x; acc0.y += acc1.y; acc0.z += acc1.z; acc0.w += acc1.w;

        acc0.x += __shfl_xor_sync(0xffffffffu, acc0.x, 16);
        acc0.y += __shfl_xor_sync(0xffffffffu, acc0.y, 16);
        acc0.z += __shfl_xor_sync(0xffffffffu, acc0.z, 16);
        acc0.w += __shfl_xor_sync(0xffffffffu, acc0.w, 16);

        if (half == 0) {
            float nv = __ldg(norm + node);
            float4 bv = reinterpret_cast<const float4*>(bias)[c16];
            acc0.x = fmaf(acc0.x, nv, bv.x);
            acc0.y = fmaf(acc0.y, nv, bv.y);
            acc0.z = fmaf(acc0.z, nv, bv.z);
            acc0.w = fmaf(acc0.w, nv, bv.w);
            reinterpret_cast<float4*>(out + (size_t)node * DIM)[c16] = acc0;
        }
    }
}

// ---------------------------------------------------------------------------
// Launch. Inputs: 0 feature [N,64] f32, 1 norm [N] f32, 2 src [E] i32,
//                 3 dst [E] i32, 4 W [64,64] f32, 5 b [64] f32. out [N,64] f32.
// ---------------------------------------------------------------------------
extern "C" void kernel_launch(void* const* d_in, const int* in_sizes, int n_in,
                              void* d_out, int out_size) {
    const float* feature = (const float*)d_in[0];
    const float* norm    = (const float*)d_in[1];
    const int*   src     = (const int*)d_in[2];
    const int*   dst     = (const int*)d_in[3];
    const float* W       = (const float*)d_in[4];
    const float* b       = (const float*)d_in[5];
    float*       out     = (float*)d_out;

    int n = in_sizes[1];
    int e = in_sizes[2];

    void* count_ptr = nullptr;
    cudaGetSymbolAddress(&count_ptr, g_count);
    cudaMemsetAsync(count_ptr, 0, (size_t)n * sizeof(int));

    // Grid sized for guaranteed co-residency (software grid barrier safety).
    int dev = 0, sms = 148, maxb = 0;
    cudaGetDevice(&dev);
    cudaDeviceGetAttribute(&sms, cudaDevAttrMultiProcessorCount, dev);
    cudaOccupancyMaxActiveBlocksPerMultiprocessor(&maxb, fused_kernel, 256, 0);
    if (maxb < 1) maxb = 1;
    unsigned G = (unsigned)(sms * maxb);

    fused_kernel<<<G, 256>>>(feature, norm, W, src, dst, b, out, n, e, G);
}

// round 14
// speedup vs baseline: 1.0559x; 1.0031x over previous
#include <cuda_runtime.h>
#include <cuda_fp16.h>
#include <cstdint>

#define N_NODES_MAX 100000
#define DIM         64
#define MAX_TILES   128      // scan tiles of 1024 -> supports n <= 131072

// ---- scratch (allocation-free rule: __device__ globals) ----
__device__ __align__(256) __half g_y16[N_NODES_MAX * DIM]; // fp16 (feature*norm)@W^T
__device__ __align__(16) int g_count[N_NODES_MAX];         // per-dst degree
__device__ __align__(16) int g_offset[N_NODES_MAX];        // ABSOLUTE offsets / cursors
__device__ int g_sorted_src[2000000];                      // src grouped by dst
__device__ int g_tilesums[MAX_TILES];                      // raw per-tile sums
__device__ unsigned g_bar_ctr = 0;                         // grid barrier (monotonic)

// ---------------------------------------------------------------------------
// Software grid barrier: generation counter, wrap-safe, deterministic across
// graph replays. REQUIRES all blocks co-resident (grid sized via occupancy).
// ---------------------------------------------------------------------------
__device__ __forceinline__ void grid_barrier(unsigned G) {
    __syncthreads();
    if (threadIdx.x == 0) {
        __threadfence();
        unsigned t = atomicAdd(&g_bar_ctr, 1u);
        unsigned base = (t / G) * G;
        for (;;) {
            unsigned c;
            asm volatile("ld.acquire.gpu.global.u32 %0, [%1];"
                         : "=r"(c) : "l"(&g_bar_ctr));
            if (c - base >= G) break;
            __nanosleep(64);
        }
    }
    __syncthreads();
}

__device__ __forceinline__ void acc_h16(float4& a, uint2 v) {
    float2 lo = __half22float2(*reinterpret_cast<__half2*>(&v.x));
    float2 hi = __half22float2(*reinterpret_cast<__half2*>(&v.y));
    a.x += lo.x; a.y += lo.y; a.z += hi.x; a.w += hi.y;
}
__device__ __forceinline__ uint2 h2add(uint2 a, uint2 b) {
    uint2 r;
    asm("add.rn.f16x2 %0, %1, %2;" : "=r"(r.x) : "r"(a.x), "r"(b.x));
    asm("add.rn.f16x2 %0, %1, %2;" : "=r"(r.y) : "r"(a.y), "r"(b.y));
    return r;
}

#define A_STRIDE 68   // padded floats per node row in smem (272B, 16B-aligned,
                      // node stride = 4 banks -> 8 nodes cover 32 banks, no conflicts)

// ---------------------------------------------------------------------------
// THE fused kernel: transform+hist | scan | fill | gather, one launch.
// Phase A now stages the 64-node feature tile in shared (coalesced LDG) —
// the old direct loads caused 8x L1-wavefront amplification (8 lines per
// LDG.128, 4x redundant fetch) and saturated L1TEX at ~70%.
// ---------------------------------------------------------------------------
__global__ void __launch_bounds__(256, 4)
fused_kernel(const float* __restrict__ feature,
             const float* __restrict__ norm,
             const float* __restrict__ W,
             const int* __restrict__ src,
             const int* __restrict__ dst,
             const float* __restrict__ bias,
             float* __restrict__ out,
             int n, int e, unsigned G) {
    __shared__ float Wt[DIM * DIM];        // Wt[i*64+j] = W[j*64+i]
    __shared__ float sA[64 * A_STRIDE];    // staged feature tile (padded)
    __shared__ int s_sums[MAX_TILES];
    __shared__ int s_warp[8];

    int tid = threadIdx.x;
    int bid = blockIdx.x;
    int lane = tid & 31, wid = tid >> 5;

    // ================= Phase A: Wt stage + histogram + transform ===========
    for (int k = tid; k < DIM * DIM; k += 256) {
        int j = k >> 6, i = k & 63;
        Wt[i * DIM + j] = W[k];
    }
    for (int i = bid * 256 + tid; i < e; i += (int)G * 256)
        atomicAdd(&g_count[__ldg(dst + i)], 1);
    __syncthreads();

    int ntiles64 = (n + 63) >> 6;
    int node_local = tid >> 2;
    int jg = (tid & 3) * 16;
    for (int tile = bid; tile < ntiles64; tile += (int)G) {
        int tbase = tile * 64;

        // ---- stage feature tile: fully coalesced LDG.128 ----
        __syncthreads();   // previous iteration's sA reads complete
        {
            const float4* fg = reinterpret_cast<const float4*>(feature);
#pragma unroll
            for (int f = tid; f < 1024; f += 256) {
                int nd = f >> 4, i4 = f & 15;
                float4 v = make_float4(0.f, 0.f, 0.f, 0.f);
                if (tbase + nd < n) v = fg[(size_t)(tbase + nd) * 16 + i4];
                *reinterpret_cast<float4*>(&sA[nd * A_STRIDE + i4 * 4]) = v;
            }
        }
        __syncthreads();

        int node = tbase + node_local;
        if (node < n) {
            float nv = __ldg(norm + node);

            unsigned long long a01, a23, a45, a67, a89, aab, acd, aef;
            asm("mov.b64 %0, {%1, %1};" : "=l"(a01) : "f"(0.0f));
            a23 = a01; a45 = a01; a67 = a01; a89 = a01; aab = a01; acd = a01; aef = a01;

            const float* a_row = &sA[node_local * A_STRIDE];
#pragma unroll
            for (int i4 = 0; i4 < 16; i4++) {
                float4 a = *reinterpret_cast<const float4*>(&a_row[i4 * 4]);
                a.x *= nv; a.y *= nv; a.z *= nv; a.w *= nv;
                const float av[4] = {a.x, a.y, a.z, a.w};
#pragma unroll
                for (int c = 0; c < 4; c++) {
                    int i = i4 * 4 + c;
                    unsigned long long aa;
                    asm("mov.b64 %0, {%1, %1};" : "=l"(aa) : "f"(av[c]));
                    const ulonglong2* wp = reinterpret_cast<const ulonglong2*>(&Wt[i * DIM + jg]);
                    ulonglong2 w0 = wp[0], w1 = wp[1];
                    asm("fma.rn.f32x2 %0, %1, %2, %0;" : "+l"(a01) : "l"(aa), "l"(w0.x));
                    asm("fma.rn.f32x2 %0, %1, %2, %0;" : "+l"(a23) : "l"(aa), "l"(w0.y));
                    asm("fma.rn.f32x2 %0, %1, %2, %0;" : "+l"(a45) : "l"(aa), "l"(w1.x));
                    asm("fma.rn.f32x2 %0, %1, %2, %0;" : "+l"(a67) : "l"(aa), "l"(w1.y));
                    const ulonglong2* wq = reinterpret_cast<const ulonglong2*>(&Wt[i * DIM + jg + 8]);
                    ulonglong2 w2 = wq[0], w3 = wq[1];
                    asm("fma.rn.f32x2 %0, %1, %2, %0;" : "+l"(a89) : "l"(aa), "l"(w2.x));
                    asm("fma.rn.f32x2 %0, %1, %2, %0;" : "+l"(aab) : "l"(aa), "l"(w2.y));
                    asm("fma.rn.f32x2 %0, %1, %2, %0;" : "+l"(acd) : "l"(aa), "l"(w3.x));
                    asm("fma.rn.f32x2 %0, %1, %2, %0;" : "+l"(aef) : "l"(aa), "l"(w3.y));
                }
            }

            float r[16];
            asm("mov.b64 {%0, %1}, %2;" : "=f"(r[0]), "=f"(r[1]) : "l"(a01));
            asm("mov.b64 {%0, %1}, %2;" : "=f"(r[2]), "=f"(r[3]) : "l"(a23));
            asm("mov.b64 {%0, %1}, %2;" : "=f"(r[4]), "=f"(r[5]) : "l"(a45));
            asm("mov.b64 {%0, %1}, %2;" : "=f"(r[6]), "=f"(r[7]) : "l"(a67));
            asm("mov.b64 {%0, %1}, %2;" : "=f"(r[8]), "=f"(r[9]) : "l"(a89));
            asm("mov.b64 {%0, %1}, %2;" : "=f"(r[10]), "=f"(r[11]) : "l"(aab));
            asm("mov.b64 {%0, %1}, %2;" : "=f"(r[12]), "=f"(r[13]) : "l"(acd));
            asm("mov.b64 {%0, %1}, %2;" : "=f"(r[14]), "=f"(r[15]) : "l"(aef));

            uint4 p0, p1;
            __half2 h;
            h = __floats2half2_rn(r[0],  r[1]);  p0.x = *reinterpret_cast<uint32_t*>(&h);
            h = __floats2half2_rn(r[2],  r[3]);  p0.y = *reinterpret_cast<uint32_t*>(&h);
            h = __floats2half2_rn(r[4],  r[5]);  p0.z = *reinterpret_cast<uint32_t*>(&h);
            h = __floats2half2_rn(r[6],  r[7]);  p0.w = *reinterpret_cast<uint32_t*>(&h);
            h = __floats2half2_rn(r[8],  r[9]);  p1.x = *reinterpret_cast<uint32_t*>(&h);
            h = __floats2half2_rn(r[10], r[11]); p1.y = *reinterpret_cast<uint32_t*>(&h);
            h = __floats2half2_rn(r[12], r[13]); p1.z = *reinterpret_cast<uint32_t*>(&h);
            h = __floats2half2_rn(r[14], r[15]); p1.w = *reinterpret_cast<uint32_t*>(&h);
            uint4* yp = reinterpret_cast<uint4*>(g_y16 + (size_t)node * DIM + jg);
            yp[0] = p0;
            yp[1] = p1;
        }
    }

    grid_barrier(G);

    // ================= Phase B1: raw tile sums (tiles of 1024) =============
    int nst = (n + 1023) >> 10;
    for (int t = bid; t < nst; t += (int)G) {
        int base = t * 1024 + tid * 4;
        int s = 0;
        if (base + 3 < n) {
            int4 v = *reinterpret_cast<const int4*>(g_count + base);
            s = v.x + v.y + v.z + v.w;
        } else {
            for (int j = 0; j < 4 && base + j < n; j++) s += g_count[base + j];
        }
#pragma unroll
        for (int d = 16; d > 0; d >>= 1)
            s += __shfl_xor_sync(0xffffffffu, s, d);
        if (lane == 0) s_warp[wid] = s;
        __syncthreads();
        if (tid == 0) {
            int tot = 0;
#pragma unroll
            for (int j = 0; j < 8; j++) tot += s_warp[j];
            g_tilesums[t] = tot;
        }
        __syncthreads();
    }

    grid_barrier(G);

    // ===== Phase B2: every block scans tile sums (redundant) + own tiles ====
    {
        int v0 = 0;
        if (tid < MAX_TILES) {
            v0 = (tid < nst) ? g_tilesums[tid] : 0;
            s_sums[tid] = v0;
        }
        __syncthreads();
#pragma unroll
        for (int d = 1; d < MAX_TILES; d <<= 1) {
            int t = (tid < MAX_TILES && tid >= d) ? s_sums[tid - d] : 0;
            __syncthreads();
            if (tid < MAX_TILES) s_sums[tid] += t;
            __syncthreads();
        }
        if (tid < MAX_TILES) s_sums[tid] -= v0;   // exclusive
        __syncthreads();
    }
    for (int t = bid; t < nst; t += (int)G) {
        int tile_base = s_sums[t];
        int base = t * 1024 + tid * 4;
        int4 v = make_int4(0, 0, 0, 0);
        if (base + 3 < n) {
            v = *reinterpret_cast<const int4*>(g_count + base);
        } else {
            if (base + 0 < n) v.x = g_count[base + 0];
            if (base + 1 < n) v.y = g_count[base + 1];
            if (base + 2 < n) v.z = g_count[base + 2];
            if (base + 3 < n) v.w = g_count[base + 3];
        }
        int s1 = v.x + v.y, s2 = s1 + v.z, s3 = s2 + v.w;
        int tsum = s3;
        int p = tsum;
#pragma unroll
        for (int d = 1; d < 32; d <<= 1) {
            int t2 = __shfl_up_sync(0xffffffffu, p, d);
            if (lane >= d) p += t2;
        }
        if (lane == 31) s_warp[wid] = p;
        __syncthreads();
        if (wid == 0 && lane < 8) {
            int w = s_warp[lane];
            int q = w;
#pragma unroll
            for (int d = 1; d < 8; d <<= 1) {
                int t2 = __shfl_up_sync(0xffu, q, d);
                if (lane >= d) q += t2;
            }
            s_warp[lane] = q - w;
        }
        __syncthreads();
        int excl = tile_base + s_warp[wid] + (p - tsum);
        if (base + 0 < n) g_offset[base + 0] = excl;
        if (base + 1 < n) g_offset[base + 1] = excl + v.x;
        if (base + 2 < n) g_offset[base + 2] = excl + s1;
        if (base + 3 < n) g_offset[base + 3] = excl + s2;
        __syncthreads();
    }

    grid_barrier(G);

    // ================= Phase C: fill (absolute cursors) =====================
    int nq = (e + 3) >> 2;
    for (int q = bid * 256 + tid; q < nq; q += (int)G * 256) {
        int i = q * 4;
        if (i + 4 <= e) {
            int4 d4 = __ldg(reinterpret_cast<const int4*>(dst + i));
            int4 s4 = __ldg(reinterpret_cast<const int4*>(src + i));
            int p0 = atomicAdd(&g_offset[d4.x], 1);
            int p1 = atomicAdd(&g_offset[d4.y], 1);
            int p2 = atomicAdd(&g_offset[d4.z], 1);
            int p3 = atomicAdd(&g_offset[d4.w], 1);
            g_sorted_src[p0] = s4.x;
            g_sorted_src[p1] = s4.y;
            g_sorted_src[p2] = s4.z;
            g_sorted_src[p3] = s4.w;
        } else {
            for (; i < e; i++) {
                int d = __ldg(dst + i);
                int p = atomicAdd(&g_offset[d], 1);
                g_sorted_src[p] = __ldg(src + i);
            }
        }
    }

    grid_barrier(G);

    // ================= Phase D: gather + epilogue ===========================
    // After fill, g_offset[node] == absolute END of node's edge range.
    int half = lane >> 4;
    int c16  = lane & 15;
    const uint2* __restrict__ y2 = reinterpret_cast<const uint2*>(g_y16);
    for (int node = bid * 8 + wid; node < n; node += (int)G * 8) {
        int deg = __ldg(g_count + node);
        int end = __ldg(g_offset + node);
        int k   = end - deg;

        float4 acc0 = make_float4(0.f, 0.f, 0.f, 0.f);
        float4 acc1 = make_float4(0.f, 0.f, 0.f, 0.f);

        for (; k + 8 <= end; k += 8) {
            int s0 = __ldg(g_sorted_src + k + 0 + half);
            int s1 = __ldg(g_sorted_src + k + 2 + half);
            int s2 = __ldg(g_sorted_src + k + 4 + half);
            int s3 = __ldg(g_sorted_src + k + 6 + half);
            uint2 v0 = __ldg(y2 + (size_t)s0 * 16 + c16);
            uint2 v1 = __ldg(y2 + (size_t)s1 * 16 + c16);
            uint2 v2 = __ldg(y2 + (size_t)s2 * 16 + c16);
            uint2 v3 = __ldg(y2 + (size_t)s3 * 16 + c16);
            acc_h16(acc0, h2add(h2add(v0, v1), h2add(v2, v3)));
        }
        if (k + 4 <= end) {
            int s0 = __ldg(g_sorted_src + k + 0 + half);
            int s1 = __ldg(g_sorted_src + k + 2 + half);
            uint2 v0 = __ldg(y2 + (size_t)s0 * 16 + c16);
            uint2 v1 = __ldg(y2 + (size_t)s1 * 16 + c16);
            acc_h16(acc1, h2add(v0, v1));
            k += 4;
        }
        if (k + 2 <= end) {
            int s = __ldg(g_sorted_src + k + half);
            uint2 v = __ldg(y2 + (size_t)s * 16 + c16);
            acc_h16(acc0, v);
            k += 2;
        }
        if (k < end && half == 0) {
            int s = __ldg(g_sorted_src + k);
            uint2 v = __ldg(y2 + (size_t)s * 16 + c16);
            acc_h16(acc1, v);
        }

        acc0.x += acc1.x; acc0.y += acc1.y; acc0.z += acc1.z; acc0.w += acc1.w;

        acc0.x += __shfl_xor_sync(0xffffffffu, acc0.x, 16);
        acc0.y += __shfl_xor_sync(0xffffffffu, acc0.y, 16);
        acc0.z += __shfl_xor_sync(0xffffffffu, acc0.z, 16);
        acc0.w += __shfl_xor_sync(0xffffffffu, acc0.w, 16);

        if (half == 0) {
            float nv = __ldg(norm + node);
            float4 bv = reinterpret_cast<const float4*>(bias)[c16];
            acc0.x = fmaf(acc0.x, nv, bv.x);
            acc0.y = fmaf(acc0.y, nv, bv.y);
            acc0.z = fmaf(acc0.z, nv, bv.z);
            acc0.w = fmaf(acc0.w, nv, bv.w);
            reinterpret_cast<float4*>(out + (size_t)node * DIM)[c16] = acc0;
        }
    }
}

// ---------------------------------------------------------------------------
// Launch. Inputs: 0 feature [N,64] f32, 1 norm [N] f32, 2 src [E] i32,
//                 3 dst [E] i32, 4 W [64,64] f32, 5 b [64] f32. out [N,64] f32.
// ---------------------------------------------------------------------------
extern "C" void kernel_launch(void* const* d_in, const int* in_sizes, int n_in,
                              void* d_out, int out_size) {
    const float* feature = (const float*)d_in[0];
    const float* norm    = (const float*)d_in[1];
    const int*   src     = (const int*)d_in[2];
    const int*   dst     = (const int*)d_in[3];
    const float* W       = (const float*)d_in[4];
    const float* b       = (const float*)d_in[5];
    float*       out     = (float*)d_out;

    int n = in_sizes[1];
    int e = in_sizes[2];

    void* count_ptr = nullptr;
    cudaGetSymbolAddress(&count_ptr, g_count);
    cudaMemsetAsync(count_ptr, 0, (size_t)n * sizeof(int));

    // Grid sized for guaranteed co-residency (software grid barrier safety).
    int dev = 0, sms = 148, maxb = 0;
    cudaGetDevice(&dev);
    cudaDeviceGetAttribute(&sms, cudaDevAttrMultiProcessorCount, dev);
    cudaOccupancyMaxActiveBlocksPerMultiprocessor(&maxb, fused_kernel, 256, 0);
    if (maxb < 1) maxb = 1;
    unsigned G = (unsigned)(sms * maxb);

    fused_kernel<<<G, 256>>>(feature, norm, W, src, dst, b, out, n, e, G);
}

// round 15
// speedup vs baseline: 1.6296x; 1.5434x over previous
#include <cuda_runtime.h>
#include <cuda_fp16.h>
#include <cstdint>

#define N_NODES_MAX 100000
#define DIM         64
#define MAX_TILES   128      // scan tiles of 1024 -> supports n <= 131072

// ---- scratch (allocation-free rule: __device__ globals) ----
__device__ __align__(256) __half g_y16[N_NODES_MAX * DIM]; // fp16 (feature*norm)@W^T
__device__ __align__(16) int g_count[N_NODES_MAX];         // per-dst degree
__device__ __align__(16) int g_offset[N_NODES_MAX];        // ABSOLUTE offsets / cursors
__device__ int g_sorted_src[2000000];                      // src grouped by dst
__device__ int g_tilesums[MAX_TILES];                      // raw per-tile sums
__device__ unsigned g_bar_ctr = 0;                         // grid barrier (monotonic)

// ---------------------------------------------------------------------------
// Software grid barrier: generation counter, wrap-safe, deterministic across
// graph replays. REQUIRES all blocks co-resident (grid sized via occupancy).
// ---------------------------------------------------------------------------
__device__ __forceinline__ void grid_barrier(unsigned G) {
    __syncthreads();
    if (threadIdx.x == 0) {
        __threadfence();
        unsigned t = atomicAdd(&g_bar_ctr, 1u);
        unsigned base = (t / G) * G;
        for (;;) {
            unsigned c;
            asm volatile("ld.acquire.gpu.global.u32 %0, [%1];"
                         : "=r"(c) : "l"(&g_bar_ctr));
            if (c - base >= G) break;
            __nanosleep(64);
        }
    }
    __syncthreads();
}

__device__ __forceinline__ void acc_h16(float4& a, uint2 v) {
    float2 lo = __half22float2(*reinterpret_cast<__half2*>(&v.x));
    float2 hi = __half22float2(*reinterpret_cast<__half2*>(&v.y));
    a.x += lo.x; a.y += lo.y; a.z += hi.x; a.w += hi.y;
}
__device__ __forceinline__ uint2 h2add(uint2 a, uint2 b) {
    uint2 r;
    asm("add.rn.f16x2 %0, %1, %2;" : "=r"(r.x) : "r"(a.x), "r"(b.x));
    asm("add.rn.f16x2 %0, %1, %2;" : "=r"(r.y) : "r"(a.y), "r"(b.y));
    return r;
}

#define A_STRIDE 68   // padded floats per node row in smem: node stride = 4
                      // banks -> 8 consecutive nodes (quarter-warp) span all
                      // 32 banks -> conflict-free LDS.128

// ---------------------------------------------------------------------------
// THE fused kernel: transform+hist | scan | fill | gather, one launch.
// GEMM thread map: node = tid&63, jg = (tid>>6)*16 -> every warp has ONE jg,
// so all Wt LDS.128 are single-address warp BROADCASTS (1 crossbar phase
// instead of 4). The old map (jg = tid&3) moved 512B/warp-LDS for 64B of
// distinct data and saturated the smem crossbar (L1TEX ~68%).
// ---------------------------------------------------------------------------
__global__ void __launch_bounds__(256, 4)
fused_kernel(const float* __restrict__ feature,
             const float* __restrict__ norm,
             const float* __restrict__ W,
             const int* __restrict__ src,
             const int* __restrict__ dst,
             const float* __restrict__ bias,
             float* __restrict__ out,
             int n, int e, unsigned G) {
    __shared__ float Wt[DIM * DIM];        // Wt[i*64+j] = W[j*64+i]
    __shared__ float sA[64 * A_STRIDE];    // staged feature tile (padded)
    __shared__ int s_sums[MAX_TILES];
    __shared__ int s_warp[8];

    int tid = threadIdx.x;
    int bid = blockIdx.x;
    int lane = tid & 31, wid = tid >> 5;

    // ================= Phase A: Wt stage + histogram + transform ===========
    for (int k = tid; k < DIM * DIM; k += 256) {
        int j = k >> 6, i = k & 63;
        Wt[i * DIM + j] = W[k];
    }
    for (int i = bid * 256 + tid; i < e; i += (int)G * 256)
        atomicAdd(&g_count[__ldg(dst + i)], 1);
    __syncthreads();

    int ntiles64 = (n + 63) >> 6;
    int node_local = tid & 63;          // 64 nodes per tile
    int jg = (tid >> 6) * 16;           // warp-uniform column group
    for (int tile = bid; tile < ntiles64; tile += (int)G) {
        int tbase = tile * 64;

        // ---- stage feature tile: fully coalesced LDG.128 ----
        __syncthreads();   // previous iteration's sA reads complete
        {
            const float4* fg = reinterpret_cast<const float4*>(feature);
#pragma unroll
            for (int f = tid; f < 1024; f += 256) {
                int nd = f >> 4, i4 = f & 15;
                float4 v = make_float4(0.f, 0.f, 0.f, 0.f);
                if (tbase + nd < n) v = fg[(size_t)(tbase + nd) * 16 + i4];
                *reinterpret_cast<float4*>(&sA[nd * A_STRIDE + i4 * 4]) = v;
            }
        }
        __syncthreads();

        int node = tbase + node_local;
        if (node < n) {
            float nv = __ldg(norm + node);

            unsigned long long a01, a23, a45, a67, a89, aab, acd, aef;
            asm("mov.b64 %0, {%1, %1};" : "=l"(a01) : "f"(0.0f));
            a23 = a01; a45 = a01; a67 = a01; a89 = a01; aab = a01; acd = a01; aef = a01;

            const float* a_row = &sA[node_local * A_STRIDE];
#pragma unroll
            for (int i4 = 0; i4 < 16; i4++) {
                float4 a = *reinterpret_cast<const float4*>(&a_row[i4 * 4]);
                a.x *= nv; a.y *= nv; a.z *= nv; a.w *= nv;
                const float av[4] = {a.x, a.y, a.z, a.w};
#pragma unroll
                for (int c = 0; c < 4; c++) {
                    int i = i4 * 4 + c;
                    unsigned long long aa;
                    asm("mov.b64 %0, {%1, %1};" : "=l"(aa) : "f"(av[c]));
                    const ulonglong2* wp = reinterpret_cast<const ulonglong2*>(&Wt[i * DIM + jg]);
                    ulonglong2 w0 = wp[0], w1 = wp[1];
                    asm("fma.rn.f32x2 %0, %1, %2, %0;" : "+l"(a01) : "l"(aa), "l"(w0.x));
                    asm("fma.rn.f32x2 %0, %1, %2, %0;" : "+l"(a23) : "l"(aa), "l"(w0.y));
                    asm("fma.rn.f32x2 %0, %1, %2, %0;" : "+l"(a45) : "l"(aa), "l"(w1.x));
                    asm("fma.rn.f32x2 %0, %1, %2, %0;" : "+l"(a67) : "l"(aa), "l"(w1.y));
                    const ulonglong2* wq = reinterpret_cast<const ulonglong2*>(&Wt[i * DIM + jg + 8]);
                    ulonglong2 w2 = wq[0], w3 = wq[1];
                    asm("fma.rn.f32x2 %0, %1, %2, %0;" : "+l"(a89) : "l"(aa), "l"(w2.x));
                    asm("fma.rn.f32x2 %0, %1, %2, %0;" : "+l"(aab) : "l"(aa), "l"(w2.y));
                    asm("fma.rn.f32x2 %0, %1, %2, %0;" : "+l"(acd) : "l"(aa), "l"(w3.x));
                    asm("fma.rn.f32x2 %0, %1, %2, %0;" : "+l"(aef) : "l"(aa), "l"(w3.y));
                }
            }

            float r[16];
            asm("mov.b64 {%0, %1}, %2;" : "=f"(r[0]), "=f"(r[1]) : "l"(a01));
            asm("mov.b64 {%0, %1}, %2;" : "=f"(r[2]), "=f"(r[3]) : "l"(a23));
            asm("mov.b64 {%0, %1}, %2;" : "=f"(r[4]), "=f"(r[5]) : "l"(a45));
            asm("mov.b64 {%0, %1}, %2;" : "=f"(r[6]), "=f"(r[7]) : "l"(a67));
            asm("mov.b64 {%0, %1}, %2;" : "=f"(r[8]), "=f"(r[9]) : "l"(a89));
            asm("mov.b64 {%0, %1}, %2;" : "=f"(r[10]), "=f"(r[11]) : "l"(aab));
            asm("mov.b64 {%0, %1}, %2;" : "=f"(r[12]), "=f"(r[13]) : "l"(acd));
            asm("mov.b64 {%0, %1}, %2;" : "=f"(r[14]), "=f"(r[15]) : "l"(aef));

            uint4 p0, p1;
            __half2 h;
            h = __floats2half2_rn(r[0],  r[1]);  p0.x = *reinterpret_cast<uint32_t*>(&h);
            h = __floats2half2_rn(r[2],  r[3]);  p0.y = *reinterpret_cast<uint32_t*>(&h);
            h = __floats2half2_rn(r[4],  r[5]);  p0.z = *reinterpret_cast<uint32_t*>(&h);
            h = __floats2half2_rn(r[6],  r[7]);  p0.w = *reinterpret_cast<uint32_t*>(&h);
            h = __floats2half2_rn(r[8],  r[9]);  p1.x = *reinterpret_cast<uint32_t*>(&h);
            h = __floats2half2_rn(r[10], r[11]); p1.y = *reinterpret_cast<uint32_t*>(&h);
            h = __floats2half2_rn(r[12], r[13]); p1.z = *reinterpret_cast<uint32_t*>(&h);
            h = __floats2half2_rn(r[14], r[15]); p1.w = *reinterpret_cast<uint32_t*>(&h);
            uint4* yp = reinterpret_cast<uint4*>(g_y16 + (size_t)node * DIM + jg);
            yp[0] = p0;
            yp[1] = p1;
        }
    }

    grid_barrier(G);

    // ================= Phase B1: raw tile sums (tiles of 1024) =============
    int nst = (n + 1023) >> 10;
    for (int t = bid; t < nst; t += (int)G) {
        int base = t * 1024 + tid * 4;
        int s = 0;
        if (base + 3 < n) {
            int4 v = *reinterpret_cast<const int4*>(g_count + base);
            s = v.x + v.y + v.z + v.w;
        } else {
            for (int j = 0; j < 4 && base + j < n; j++) s += g_count[base + j];
        }
#pragma unroll
        for (int d = 16; d > 0; d >>= 1)
            s += __shfl_xor_sync(0xffffffffu, s, d);
        if (lane == 0) s_warp[wid] = s;
        __syncthreads();
        if (tid == 0) {
            int tot = 0;
#pragma unroll
            for (int j = 0; j < 8; j++) tot += s_warp[j];
            g_tilesums[t] = tot;
        }
        __syncthreads();
    }

    grid_barrier(G);

    // ===== Phase B2: every block scans tile sums (redundant) + own tiles ====
    {
        int v0 = 0;
        if (tid < MAX_TILES) {
            v0 = (tid < nst) ? g_tilesums[tid] : 0;
            s_sums[tid] = v0;
        }
        __syncthreads();
#pragma unroll
        for (int d = 1; d < MAX_TILES; d <<= 1) {
            int t = (tid < MAX_TILES && tid >= d) ? s_sums[tid - d] : 0;
            __syncthreads();
            if (tid < MAX_TILES) s_sums[tid] += t;
            __syncthreads();
        }
        if (tid < MAX_TILES) s_sums[tid] -= v0;   // exclusive
        __syncthreads();
    }
    for (int t = bid; t < nst; t += (int)G) {
        int tile_base = s_sums[t];
        int base = t * 1024 + tid * 4;
        int4 v = make_int4(0, 0, 0, 0);
        if (base + 3 < n) {
            v = *reinterpret_cast<const int4*>(g_count + base);
        } else {
            if (base + 0 < n) v.x = g_count[base + 0];
            if (base + 1 < n) v.y = g_count[base + 1];
            if (base + 2 < n) v.z = g_count[base + 2];
            if (base + 3 < n) v.w = g_count[base + 3];
        }
        int s1 = v.x + v.y, s2 = s1 + v.z, s3 = s2 + v.w;
        int tsum = s3;
        int p = tsum;
#pragma unroll
        for (int d = 1; d < 32; d <<= 1) {
            int t2 = __shfl_up_sync(0xffffffffu, p, d);
            if (lane >= d) p += t2;
        }
        if (lane == 31) s_warp[wid] = p;
        __syncthreads();
        if (wid == 0 && lane < 8) {
            int w = s_warp[lane];
            int q = w;
#pragma unroll
            for (int d = 1; d < 8; d <<= 1) {
                int t2 = __shfl_up_sync(0xffu, q, d);
                if (lane >= d) q += t2;
            }
            s_warp[lane] = q - w;
        }
        __syncthreads();
        int excl = tile_base + s_warp[wid] + (p - tsum);
        if (base + 0 < n) g_offset[base + 0] = excl;
        if (base + 1 < n) g_offset[base + 1] = excl + v.x;
        if (base + 2 < n) g_offset[base + 2] = excl + s1;
        if (base + 3 < n) g_offset[base + 3] = excl + s2;
        __syncthreads();
    }

    grid_barrier(G);

    // ================= Phase C: fill (absolute cursors) =====================
    int nq = (e + 3) >> 2;
    for (int q = bid * 256 + tid; q < nq; q += (int)G * 256) {
        int i = q * 4;
        if (i + 4 <= e) {
            int4 d4 = __ldg(reinterpret_cast<const int4*>(dst + i));
            int4 s4 = __ldg(reinterpret_cast<const int4*>(src + i));
            int p0 = atomicAdd(&g_offset[d4.x], 1);
            int p1 = atomicAdd(&g_offset[d4.y], 1);
            int p2 = atomicAdd(&g_offset[d4.z], 1);
            int p3 = atomicAdd(&g_offset[d4.w], 1);
            g_sorted_src[p0] = s4.x;
            g_sorted_src[p1] = s4.y;
            g_sorted_src[p2] = s4.z;
            g_sorted_src[p3] = s4.w;
        } else {
            for (; i < e; i++) {
                int d = __ldg(dst + i);
                int p = atomicAdd(&g_offset[d], 1);
                g_sorted_src[p] = __ldg(src + i);
            }
        }
    }

    grid_barrier(G);

    // ================= Phase D: gather + epilogue ===========================
    // After fill, g_offset[node] == absolute END of node's edge range.
    int half = lane >> 4;
    int c16  = lane & 15;
    const uint2* __restrict__ y2 = reinterpret_cast<const uint2*>(g_y16);
    for (int node = bid * 8 + wid; node < n; node += (int)G * 8) {
        int deg = __ldg(g_count + node);
        int end = __ldg(g_offset + node);
        int k   = end - deg;

        float4 acc0 = make_float4(0.f, 0.f, 0.f, 0.f);
        float4 acc1 = make_float4(0.f, 0.f, 0.f, 0.f);

        for (; k + 8 <= end; k += 8) {
            int s0 = __ldg(g_sorted_src + k + 0 + half);
            int s1 = __ldg(g_sorted_src + k + 2 + half);
            int s2 = __ldg(g_sorted_src + k + 4 + half);
            int s3 = __ldg(g_sorted_src + k + 6 + half);
            uint2 v0 = __ldg(y2 + (size_t)s0 * 16 + c16);
            uint2 v1 = __ldg(y2 + (size_t)s1 * 16 + c16);
            uint2 v2 = __ldg(y2 + (size_t)s2 * 16 + c16);
            uint2 v3 = __ldg(y2 + (size_t)s3 * 16 + c16);
            acc_h16(acc0, h2add(h2add(v0, v1), h2add(v2, v3)));
        }
        if (k + 4 <= end) {
            int s0 = __ldg(g_sorted_src + k + 0 + half);
            int s1 = __ldg(g_sorted_src + k + 2 + half);
            uint2 v0 = __ldg(y2 + (size_t)s0 * 16 + c16);
            uint2 v1 = __ldg(y2 + (size_t)s1 * 16 + c16);
            acc_h16(acc1, h2add(v0, v1));
            k += 4;
        }
        if (k + 2 <= end) {
            int s = __ldg(g_sorted_src + k + half);
            uint2 v = __ldg(y2 + (size_t)s * 16 + c16);
            acc_h16(acc0, v);
            k += 2;
        }
        if (k < end && half == 0) {
            int s = __ldg(g_sorted_src + k);
            uint2 v = __ldg(y2 + (size_t)s * 16 + c16);
            acc_h16(acc1, v);
        }

        acc0.x += acc1.x; acc0.y += acc1.y; acc0.z += acc1.z; acc0.w += acc1.w;

        acc0.x += __shfl_xor_sync(0xffffffffu, acc0.x, 16);
        acc0.y += __shfl_xor_sync(0xffffffffu, acc0.y, 16);
        acc0.z += __shfl_xor_sync(0xffffffffu, acc0.z, 16);
        acc0.w += __shfl_xor_sync(0xffffffffu, acc0.w, 16);

        if (half == 0) {
            float nv = __ldg(norm + node);
            float4 bv = reinterpret_cast<const float4*>(bias)[c16];
            acc0.x = fmaf(acc0.x, nv, bv.x);
            acc0.y = fmaf(acc0.y, nv, bv.y);
            acc0.z = fmaf(acc0.z, nv, bv.z);
            acc0.w = fmaf(acc0.w, nv, bv.w);
            reinterpret_cast<float4*>(out + (size_t)node * DIM)[c16] = acc0;
        }
    }
}

// ---------------------------------------------------------------------------
// Launch. Inputs: 0 feature [N,64] f32, 1 norm [N] f32, 2 src [E] i32,
//                 3 dst [E] i32, 4 W [64,64] f32, 5 b [64] f32. out [N,64] f32.
// ---------------------------------------------------------------------------
extern "C" void kernel_launch(void* const* d_in, const int* in_sizes, int n_in,
                              void* d_out, int out_size) {
    const float* feature = (const float*)d_in[0];
    const float* norm    = (const float*)d_in[1];
    const int*   src     = (const int*)d_in[2];
    const int*   dst     = (const int*)d_in[3];
    const float* W       = (const float*)d_in[4];
    const float* b       = (const float*)d_in[5];
    float*       out     = (float*)d_out;

    int n = in_sizes[1];
    int e = in_sizes[2];

    void* count_ptr = nullptr;
    cudaGetSymbolAddress(&count_ptr, g_count);
    cudaMemsetAsync(count_ptr, 0, (size_t)n * sizeof(int));

    // Grid sized for guaranteed co-residency (software grid barrier safety).
    int dev = 0, sms = 148, maxb = 0;
    cudaGetDevice(&dev);
    cudaDeviceGetAttribute(&sms, cudaDevAttrMultiProcessorCount, dev);
    cudaOccupancyMaxActiveBlocksPerMultiprocessor(&maxb, fused_kernel, 256, 0);
    if (maxb < 1) maxb = 1;
    unsigned G = (unsigned)(sms * maxb);

    fused_kernel<<<G, 256>>>(feature, norm, W, src, dst, b, out, n, e, G);
}

// round 16
// speedup vs baseline: 1.6628x; 1.0204x over previous
#include <cuda_runtime.h>
#include <cuda_fp16.h>
#include <cstdint>

#define N_NODES_MAX 100000
#define DIM         64
#define MAX_TILES   128      // scan tiles of 1024 -> supports n <= 131072
#define SA_STRIDE   68       // halves per node row in sA (conflict-free phases)

// ---- scratch (allocation-free rule: __device__ globals) ----
__device__ __align__(256) __half g_y16[N_NODES_MAX * DIM]; // fp16 (feature*norm)@W^T
__device__ __align__(16) int g_count[N_NODES_MAX];         // per-dst degree
__device__ __align__(16) int g_offset[N_NODES_MAX];        // ABSOLUTE offsets / cursors
__device__ int g_sorted_src[2000000];                      // src grouped by dst
__device__ int g_tilesums[MAX_TILES];                      // raw per-tile sums
__device__ unsigned g_bar_ctr = 0;                         // grid barrier (monotonic)

// ---------------------------------------------------------------------------
// Software grid barrier: generation counter, wrap-safe, deterministic across
// graph replays. REQUIRES all blocks co-resident (grid sized via occupancy).
// ---------------------------------------------------------------------------
__device__ __forceinline__ void grid_barrier(unsigned G) {
    __syncthreads();
    if (threadIdx.x == 0) {
        __threadfence();
        unsigned t = atomicAdd(&g_bar_ctr, 1u);
        unsigned base = (t / G) * G;
        for (;;) {
            unsigned c;
            asm volatile("ld.acquire.gpu.global.u32 %0, [%1];"
                         : "=r"(c) : "l"(&g_bar_ctr));
            if (c - base >= G) break;
            __nanosleep(64);
        }
    }
    __syncthreads();
}

__device__ __forceinline__ void acc_h16(float4& a, uint2 v) {
    float2 lo = __half22float2(*reinterpret_cast<__half2*>(&v.x));
    float2 hi = __half22float2(*reinterpret_cast<__half2*>(&v.y));
    a.x += lo.x; a.y += lo.y; a.z += hi.x; a.w += hi.y;
}
__device__ __forceinline__ uint2 h2add(uint2 a, uint2 b) {
    uint2 r;
    asm("add.rn.f16x2 %0, %1, %2;" : "=r"(r.x) : "r"(a.x), "r"(b.x));
    asm("add.rn.f16x2 %0, %1, %2;" : "=r"(r.y) : "r"(a.y), "r"(b.y));
    return r;
}

// ---------------------------------------------------------------------------
// THE fused kernel: transform+hist | scan | fill | gather, one launch.
// Phase A GEMM: 128-node tiles; warp owns 8 columns (jg=wid*8, uniform ->
// W LDS are broadcasts); thread accumulates 4 nodes x 8 cols so each W
// broadcast feeds 16 FMAs (per-node LDS drops 272 -> 48). A staged in fp16.
// ---------------------------------------------------------------------------
__global__ void __launch_bounds__(256, 3)
fused_kernel(const float* __restrict__ feature,
             const float* __restrict__ norm,
             const float* __restrict__ W,
             const int* __restrict__ src,
             const int* __restrict__ dst,
             const float* __restrict__ bias,
             float* __restrict__ out,
             int n, int e, unsigned G) {
    __shared__ float Wt[DIM * DIM];            // Wt[i*64+j] = W[j*64+i]
    __shared__ __align__(16) __half sA[128 * SA_STRIDE];  // fp16 (feature*norm) tile
    __shared__ int s_sums[MAX_TILES];
    __shared__ int s_warp[8];

    int tid = threadIdx.x;
    int bid = blockIdx.x;
    int lane = tid & 31, wid = tid >> 5;

    // ================= Phase A: Wt stage + histogram + transform ===========
    for (int k = tid; k < DIM * DIM; k += 256) {
        int j = k >> 6, i = k & 63;
        Wt[i * DIM + j] = W[k];
    }
    for (int i = bid * 256 + tid; i < e; i += (int)G * 256)
        atomicAdd(&g_count[__ldg(dst + i)], 1);
    __syncthreads();

    int ntiles = (n + 127) >> 7;               // 128-node tiles
    int jg = wid * 8;                          // warp-uniform 8-column group
    for (int tile = bid; tile < ntiles; tile += (int)G) {
        int tbase = tile * 128;

        // ---- stage (feature * norm) tile as fp16: coalesced LDG.128 ----
        __syncthreads();   // previous iteration's sA reads complete
        {
            const float4* fg = reinterpret_cast<const float4*>(feature);
#pragma unroll
            for (int f = tid; f < 2048; f += 256) {
                int nd = f >> 4, i4 = f & 15;
                float4 v = make_float4(0.f, 0.f, 0.f, 0.f);
                if (tbase + nd < n) {
                    float nv = __ldg(norm + tbase + nd);
                    v = fg[(size_t)(tbase + nd) * 16 + i4];
                    v.x *= nv; v.y *= nv; v.z *= nv; v.w *= nv;
                }
                __half2 lo = __floats2half2_rn(v.x, v.y);
                __half2 hi = __floats2half2_rn(v.z, v.w);
                uint2 p;
                p.x = *reinterpret_cast<uint32_t*>(&lo);
                p.y = *reinterpret_cast<uint32_t*>(&hi);
                *reinterpret_cast<uint2*>(&sA[nd * SA_STRIDE + i4 * 4]) = p;
            }
        }
        __syncthreads();

        // ---- GEMM: 4 nodes/thread (lane, lane+32, lane+64, lane+96) ----
        unsigned long long acc[4][4];
#pragma unroll
        for (int q = 0; q < 4; q++)
#pragma unroll
            for (int c4 = 0; c4 < 4; c4++)
                asm("mov.b64 %0, {%1, %1};" : "=l"(acc[q][c4]) : "f"(0.0f));

#pragma unroll
        for (int i4 = 0; i4 < 16; i4++) {
            float4 a[4];
#pragma unroll
            for (int q = 0; q < 4; q++) {
                uint2 ah = *reinterpret_cast<const uint2*>(
                    &sA[(lane + 32 * q) * SA_STRIDE + i4 * 4]);
                float2 lo = __half22float2(*reinterpret_cast<__half2*>(&ah.x));
                float2 hi = __half22float2(*reinterpret_cast<__half2*>(&ah.y));
                a[q] = make_float4(lo.x, lo.y, hi.x, hi.y);
            }
#pragma unroll
            for (int c = 0; c < 4; c++) {
                int i = i4 * 4 + c;
                const ulonglong2* wp =
                    reinterpret_cast<const ulonglong2*>(&Wt[i * DIM + jg]);
                ulonglong2 w0 = wp[0], w1 = wp[1];   // 8 cols (broadcast)
                const float av[4] = {a[0].x, a[1].x, a[2].x, a[3].x};
                // select c-th component of each a[q]
                float a0 = (c == 0) ? a[0].x : (c == 1) ? a[0].y : (c == 2) ? a[0].z : a[0].w;
                float a1 = (c == 0) ? a[1].x : (c == 1) ? a[1].y : (c == 2) ? a[1].z : a[1].w;
                float a2 = (c == 0) ? a[2].x : (c == 1) ? a[2].y : (c == 2) ? a[2].z : a[2].w;
                float a3 = (c == 0) ? a[3].x : (c == 1) ? a[3].y : (c == 2) ? a[3].z : a[3].w;
                (void)av;
                unsigned long long s0, s1, s2, s3;
                asm("mov.b64 %0, {%1, %1};" : "=l"(s0) : "f"(a0));
                asm("mov.b64 %0, {%1, %1};" : "=l"(s1) : "f"(a1));
                asm("mov.b64 %0, {%1, %1};" : "=l"(s2) : "f"(a2));
                asm("mov.b64 %0, {%1, %1};" : "=l"(s3) : "f"(a3));
                asm("fma.rn.f32x2 %0, %1, %2, %0;" : "+l"(acc[0][0]) : "l"(s0), "l"(w0.x));
                asm("fma.rn.f32x2 %0, %1, %2, %0;" : "+l"(acc[0][1]) : "l"(s0), "l"(w0.y));
                asm("fma.rn.f32x2 %0, %1, %2, %0;" : "+l"(acc[0][2]) : "l"(s0), "l"(w1.x));
                asm("fma.rn.f32x2 %0, %1, %2, %0;" : "+l"(acc[0][3]) : "l"(s0), "l"(w1.y));
                asm("fma.rn.f32x2 %0, %1, %2, %0;" : "+l"(acc[1][0]) : "l"(s1), "l"(w0.x));
                asm("fma.rn.f32x2 %0, %1, %2, %0;" : "+l"(acc[1][1]) : "l"(s1), "l"(w0.y));
                asm("fma.rn.f32x2 %0, %1, %2, %0;" : "+l"(acc[1][2]) : "l"(s1), "l"(w1.x));
                asm("fma.rn.f32x2 %0, %1, %2, %0;" : "+l"(acc[1][3]) : "l"(s1), "l"(w1.y));
                asm("fma.rn.f32x2 %0, %1, %2, %0;" : "+l"(acc[2][0]) : "l"(s2), "l"(w0.x));
                asm("fma.rn.f32x2 %0, %1, %2, %0;" : "+l"(acc[2][1]) : "l"(s2), "l"(w0.y));
                asm("fma.rn.f32x2 %0, %1, %2, %0;" : "+l"(acc[2][2]) : "l"(s2), "l"(w1.x));
                asm("fma.rn.f32x2 %0, %1, %2, %0;" : "+l"(acc[2][3]) : "l"(s2), "l"(w1.y));
                asm("fma.rn.f32x2 %0, %1, %2, %0;" : "+l"(acc[3][0]) : "l"(s3), "l"(w0.x));
                asm("fma.rn.f32x2 %0, %1, %2, %0;" : "+l"(acc[3][1]) : "l"(s3), "l"(w0.y));
                asm("fma.rn.f32x2 %0, %1, %2, %0;" : "+l"(acc[3][2]) : "l"(s3), "l"(w1.x));
                asm("fma.rn.f32x2 %0, %1, %2, %0;" : "+l"(acc[3][3]) : "l"(s3), "l"(w1.y));
            }
        }

        // ---- store y16: 8 cols = 16B per node ----
#pragma unroll
        for (int q = 0; q < 4; q++) {
            int node = tbase + lane + 32 * q;
            if (node >= n) continue;
            float r[8];
            asm("mov.b64 {%0, %1}, %2;" : "=f"(r[0]), "=f"(r[1]) : "l"(acc[q][0]));
            asm("mov.b64 {%0, %1}, %2;" : "=f"(r[2]), "=f"(r[3]) : "l"(acc[q][1]));
            asm("mov.b64 {%0, %1}, %2;" : "=f"(r[4]), "=f"(r[5]) : "l"(acc[q][2]));
            asm("mov.b64 {%0, %1}, %2;" : "=f"(r[6]), "=f"(r[7]) : "l"(acc[q][3]));
            uint4 p;
            __half2 h;
            h = __floats2half2_rn(r[0], r[1]); p.x = *reinterpret_cast<uint32_t*>(&h);
            h = __floats2half2_rn(r[2], r[3]); p.y = *reinterpret_cast<uint32_t*>(&h);
            h = __floats2half2_rn(r[4], r[5]); p.z = *reinterpret_cast<uint32_t*>(&h);
            h = __floats2half2_rn(r[6], r[7]); p.w = *reinterpret_cast<uint32_t*>(&h);
            *reinterpret_cast<uint4*>(g_y16 + (size_t)node * DIM + jg) = p;
        }
    }

    grid_barrier(G);

    // ================= Phase B1: raw tile sums (tiles of 1024) =============
    int nst = (n + 1023) >> 10;
    for (int t = bid; t < nst; t += (int)G) {
        int base = t * 1024 + tid * 4;
        int s = 0;
        if (base + 3 < n) {
            int4 v = *reinterpret_cast<const int4*>(g_count + base);
            s = v.x + v.y + v.z + v.w;
        } else {
            for (int j = 0; j < 4 && base + j < n; j++) s += g_count[base + j];
        }
#pragma unroll
        for (int d = 16; d > 0; d >>= 1)
            s += __shfl_xor_sync(0xffffffffu, s, d);
        if (lane == 0) s_warp[wid] = s;
        __syncthreads();
        if (tid == 0) {
            int tot = 0;
#pragma unroll
            for (int j = 0; j < 8; j++) tot += s_warp[j];
            g_tilesums[t] = tot;
        }
        __syncthreads();
    }

    grid_barrier(G);

    // ===== Phase B2: every block scans tile sums (redundant) + own tiles ====
    {
        int v0 = 0;
        if (tid < MAX_TILES) {
            v0 = (tid < nst) ? g_tilesums[tid] : 0;
            s_sums[tid] = v0;
        }
        __syncthreads();
#pragma unroll
        for (int d = 1; d < MAX_TILES; d <<= 1) {
            int t = (tid < MAX_TILES && tid >= d) ? s_sums[tid - d] : 0;
            __syncthreads();
            if (tid < MAX_TILES) s_sums[tid] += t;
            __syncthreads();
        }
        if (tid < MAX_TILES) s_sums[tid] -= v0;   // exclusive
        __syncthreads();
    }
    for (int t = bid; t < nst; t += (int)G) {
        int tile_base = s_sums[t];
        int base = t * 1024 + tid * 4;
        int4 v = make_int4(0, 0, 0, 0);
        if (base + 3 < n) {
            v = *reinterpret_cast<const int4*>(g_count + base);
        } else {
            if (base + 0 < n) v.x = g_count[base + 0];
            if (base + 1 < n) v.y = g_count[base + 1];
            if (base + 2 < n) v.z = g_count[base + 2];
            if (base + 3 < n) v.w = g_count[base + 3];
        }
        int s1 = v.x + v.y, s2 = s1 + v.z, s3 = s2 + v.w;
        int tsum = s3;
        int p = tsum;
#pragma unroll
        for (int d = 1; d < 32; d <<= 1) {
            int t2 = __shfl_up_sync(0xffffffffu, p, d);
            if (lane >= d) p += t2;
        }
        if (lane == 31) s_warp[wid] = p;
        __syncthreads();
        if (wid == 0 && lane < 8) {
            int w = s_warp[lane];
            int q = w;
#pragma unroll
            for (int d = 1; d < 8; d <<= 1) {
                int t2 = __shfl_up_sync(0xffu, q, d);
                if (lane >= d) q += t2;
            }
            s_warp[lane] = q - w;
        }
        __syncthreads();
        int excl = tile_base + s_warp[wid] + (p - tsum);
        if (base + 0 < n) g_offset[base + 0] = excl;
        if (base + 1 < n) g_offset[base + 1] = excl + v.x;
        if (base + 2 < n) g_offset[base + 2] = excl + s1;
        if (base + 3 < n) g_offset[base + 3] = excl + s2;
        __syncthreads();
    }

    grid_barrier(G);

    // ================= Phase C: fill (absolute cursors) =====================
    int nq = (e + 3) >> 2;
    for (int q = bid * 256 + tid; q < nq; q += (int)G * 256) {
        int i = q * 4;
        if (i + 4 <= e) {
            int4 d4 = __ldg(reinterpret_cast<const int4*>(dst + i));
            int4 s4 = __ldg(reinterpret_cast<const int4*>(src + i));
            int p0 = atomicAdd(&g_offset[d4.x], 1);
            int p1 = atomicAdd(&g_offset[d4.y], 1);
            int p2 = atomicAdd(&g_offset[d4.z], 1);
            int p3 = atomicAdd(&g_offset[d4.w], 1);
            g_sorted_src[p0] = s4.x;
            g_sorted_src[p1] = s4.y;
            g_sorted_src[p2] = s4.z;
            g_sorted_src[p3] = s4.w;
        } else {
            for (; i < e; i++) {
                int d = __ldg(dst + i);
                int p = atomicAdd(&g_offset[d], 1);
                g_sorted_src[p] = __ldg(src + i);
            }
        }
    }

    grid_barrier(G);

    // ================= Phase D: gather + epilogue ===========================
    // After fill, g_offset[node] == absolute END of node's edge range.
    int half = lane >> 4;
    int c16  = lane & 15;
    const uint2* __restrict__ y2 = reinterpret_cast<const uint2*>(g_y16);
    for (int node = bid * 8 + wid; node < n; node += (int)G * 8) {
        int deg = __ldg(g_count + node);
        int end = __ldg(g_offset + node);
        int k   = end - deg;

        float4 acc0 = make_float4(0.f, 0.f, 0.f, 0.f);
        float4 acc1 = make_float4(0.f, 0.f, 0.f, 0.f);

        for (; k + 8 <= end; k += 8) {
            int s0 = __ldg(g_sorted_src + k + 0 + half);
            int s1 = __ldg(g_sorted_src + k + 2 + half);
            int s2 = __ldg(g_sorted_src + k + 4 + half);
            int s3 = __ldg(g_sorted_src + k + 6 + half);
            uint2 v0 = __ldg(y2 + (size_t)s0 * 16 + c16);
            uint2 v1 = __ldg(y2 + (size_t)s1 * 16 + c16);
            uint2 v2 = __ldg(y2 + (size_t)s2 * 16 + c16);
            uint2 v3 = __ldg(y2 + (size_t)s3 * 16 + c16);
            acc_h16(acc0, h2add(h2add(v0, v1), h2add(v2, v3)));
        }
        if (k + 4 <= end) {
            int s0 = __ldg(g_sorted_src + k + 0 + half);
            int s1 = __ldg(g_sorted_src + k + 2 + half);
            uint2 v0 = __ldg(y2 + (size_t)s0 * 16 + c16);
            uint2 v1 = __ldg(y2 + (size_t)s1 * 16 + c16);
            acc_h16(acc1, h2add(v0, v1));
            k += 4;
        }
        if (k + 2 <= end) {
            int s = __ldg(g_sorted_src + k + half);
            uint2 v = __ldg(y2 + (size_t)s * 16 + c16);
            acc_h16(acc0, v);
            k += 2;
        }
        if (k < end && half == 0) {
            int s = __ldg(g_sorted_src + k);
            uint2 v = __ldg(y2 + (size_t)s * 16 + c16);
            acc_h16(acc1, v);
        }

        acc0.x += acc1.x; acc0.y += acc1.y; acc0.z += acc1.z; acc0.w += acc1.w;

        acc0.x += __shfl_xor_sync(0xffffffffu, acc0.x, 16);
        acc0.y += __shfl_xor_sync(0xffffffffu, acc0.y, 16);
        acc0.z += __shfl_xor_sync(0xffffffffu, acc0.z, 16);
        acc0.w += __shfl_xor_sync(0xffffffffu, acc0.w, 16);

        if (half == 0) {
            float nv = __ldg(norm + node);
            float4 bv = reinterpret_cast<const float4*>(bias)[c16];
            acc0.x = fmaf(acc0.x, nv, bv.x);
            acc0.y = fmaf(acc0.y, nv, bv.y);
            acc0.z = fmaf(acc0.z, nv, bv.z);
            acc0.w = fmaf(acc0.w, nv, bv.w);
            reinterpret_cast<float4*>(out + (size_t)node * DIM)[c16] = acc0;
        }
    }
}

// ---------------------------------------------------------------------------
// Launch. Inputs: 0 feature [N,64] f32, 1 norm [N] f32, 2 src [E] i32,
//                 3 dst [E] i32, 4 W [64,64] f32, 5 b [64] f32. out [N,64] f32.
// ---------------------------------------------------------------------------
extern "C" void kernel_launch(void* const* d_in, const int* in_sizes, int n_in,
                              void* d_out, int out_size) {
    const float* feature = (const float*)d_in[0];
    const float* norm    = (const float*)d_in[1];
    const int*   src     = (const int*)d_in[2];
    const int*   dst     = (const int*)d_in[3];
    const float* W       = (const float*)d_in[4];
    const float* b       = (const float*)d_in[5];
    float*       out     = (float*)d_out;

    int n = in_sizes[1];
    int e = in_sizes[2];

    void* count_ptr = nullptr;
    cudaGetSymbolAddress(&count_ptr, g_count);
    cudaMemsetAsync(count_ptr, 0, (size_t)n * sizeof(int));

    // Grid sized for guaranteed co-residency (software grid barrier safety).
    int dev = 0, sms = 148, maxb = 0;
    cudaGetDevice(&dev);
    cudaDeviceGetAttribute(&sms, cudaDevAttrMultiProcessorCount, dev);
    cudaOccupancyMaxActiveBlocksPerMultiprocessor(&maxb, fused_kernel, 256, 0);
    if (maxb < 1) maxb = 1;
    unsigned G = (unsigned)(sms * maxb);

    fused_kernel<<<G, 256>>>(feature, norm, W, src, dst, b, out, n, e, G);
}

// round 17
// speedup vs baseline: 1.7207x; 1.0348x over previous
#include <cuda_runtime.h>
#include <cuda_fp16.h>
#include <cstdint>

#define N_NODES_MAX 100000
#define DIM         64
#define MAX_TILES   128      // scan tiles of 1024 -> supports n <= 131072
#define SA_STRIDE   68       // halves per node row in sA

// ---- scratch (allocation-free rule: __device__ globals) ----
__device__ __align__(256) __half g_y16[N_NODES_MAX * DIM]; // fp16 (feature*norm)@W^T
__device__ __align__(16) int g_count[N_NODES_MAX];         // per-dst degree
__device__ __align__(16) int g_offset[N_NODES_MAX];        // ABSOLUTE offsets / cursors
__device__ int g_sorted_src[2000000];                      // src grouped by dst
__device__ int g_tilesums[MAX_TILES];                      // raw per-tile sums
__device__ unsigned g_bar_ctr = 0;                         // grid barrier (monotonic)

// ---------------------------------------------------------------------------
// Software grid barrier: generation counter, wrap-safe, deterministic across
// graph replays. REQUIRES all blocks co-resident (grid sized via occupancy).
// ---------------------------------------------------------------------------
__device__ __forceinline__ void grid_barrier(unsigned G) {
    __syncthreads();
    if (threadIdx.x == 0) {
        __threadfence();
        unsigned t = atomicAdd(&g_bar_ctr, 1u);
        unsigned base = (t / G) * G;
        for (;;) {
            unsigned c;
            asm volatile("ld.acquire.gpu.global.u32 %0, [%1];"
                         : "=r"(c) : "l"(&g_bar_ctr));
            if (c - base >= G) break;
            __nanosleep(64);
        }
    }
    __syncthreads();
}

__device__ __forceinline__ void acc_h16(float4& a, uint2 v) {
    float2 lo = __half22float2(*reinterpret_cast<__half2*>(&v.x));
    float2 hi = __half22float2(*reinterpret_cast<__half2*>(&v.y));
    a.x += lo.x; a.y += lo.y; a.z += hi.x; a.w += hi.y;
}
__device__ __forceinline__ uint2 h2add(uint2 a, uint2 b) {
    uint2 r;
    asm("add.rn.f16x2 %0, %1, %2;" : "=r"(r.x) : "r"(a.x), "r"(b.x));
    asm("add.rn.f16x2 %0, %1, %2;" : "=r"(r.y) : "r"(a.y), "r"(b.y));
    return r;
}

// ---------------------------------------------------------------------------
// THE fused kernel: transform+hist | scan | fill | gather, one launch.
// Phase A GEMM: 64-node tiles; warp owns 8 columns (jg=wid*8, uniform ->
// W LDS are broadcasts); thread accumulates 2 nodes x 8 cols. This fits the
// whole kernel in <=64 regs -> __launch_bounds__(256,4) -> 50% occupancy
// (the 4-node/80-reg version throttled to 37.5% and starved gather/fill).
// ---------------------------------------------------------------------------
__global__ void __launch_bounds__(256, 4)
fused_kernel(const float* __restrict__ feature,
             const float* __restrict__ norm,
             const float* __restrict__ W,
             const int* __restrict__ src,
             const int* __restrict__ dst,
             const float* __restrict__ bias,
             float* __restrict__ out,
             int n, int e, unsigned G) {
    __shared__ float Wt[DIM * DIM];                        // Wt[i*64+j] = W[j*64+i]
    __shared__ __align__(16) __half sA[64 * SA_STRIDE];    // fp16 (feature*norm) tile
    __shared__ int s_sums[MAX_TILES];
    __shared__ int s_warp[8];

    int tid = threadIdx.x;
    int bid = blockIdx.x;
    int lane = tid & 31, wid = tid >> 5;

    // ================= Phase A: Wt stage + histogram + transform ===========
    for (int k = tid; k < DIM * DIM; k += 256) {
        int j = k >> 6, i = k & 63;
        Wt[i * DIM + j] = W[k];
    }
    for (int i = bid * 256 + tid; i < e; i += (int)G * 256)
        atomicAdd(&g_count[__ldg(dst + i)], 1);
    __syncthreads();

    int ntiles = (n + 63) >> 6;                // 64-node tiles
    int jg = wid * 8;                          // warp-uniform 8-column group
    for (int tile = bid; tile < ntiles; tile += (int)G) {
        int tbase = tile * 64;

        // ---- stage (feature * norm) tile as fp16: coalesced LDG.128 ----
        __syncthreads();   // previous iteration's sA reads complete
        {
            const float4* fg = reinterpret_cast<const float4*>(feature);
#pragma unroll
            for (int f = tid; f < 1024; f += 256) {
                int nd = f >> 4, i4 = f & 15;
                float4 v = make_float4(0.f, 0.f, 0.f, 0.f);
                if (tbase + nd < n) {
                    float nv = __ldg(norm + tbase + nd);
                    v = fg[(size_t)(tbase + nd) * 16 + i4];
                    v.x *= nv; v.y *= nv; v.z *= nv; v.w *= nv;
                }
                __half2 lo = __floats2half2_rn(v.x, v.y);
                __half2 hi = __floats2half2_rn(v.z, v.w);
                uint2 p;
                p.x = *reinterpret_cast<uint32_t*>(&lo);
                p.y = *reinterpret_cast<uint32_t*>(&hi);
                *reinterpret_cast<uint2*>(&sA[nd * SA_STRIDE + i4 * 4]) = p;
            }
        }
        __syncthreads();

        // ---- GEMM: 2 nodes/thread (lane, lane+32) x 8 cols ----
        unsigned long long acc[2][4];
#pragma unroll
        for (int q = 0; q < 2; q++)
#pragma unroll
            for (int c4 = 0; c4 < 4; c4++)
                asm("mov.b64 %0, {%1, %1};" : "=l"(acc[q][c4]) : "f"(0.0f));

#pragma unroll
        for (int i4 = 0; i4 < 16; i4++) {
            float a[2][4];
#pragma unroll
            for (int q = 0; q < 2; q++) {
                uint2 ah = *reinterpret_cast<const uint2*>(
                    &sA[(lane + 32 * q) * SA_STRIDE + i4 * 4]);
                float2 lo = __half22float2(*reinterpret_cast<__half2*>(&ah.x));
                float2 hi = __half22float2(*reinterpret_cast<__half2*>(&ah.y));
                a[q][0] = lo.x; a[q][1] = lo.y; a[q][2] = hi.x; a[q][3] = hi.y;
            }
#pragma unroll
            for (int c = 0; c < 4; c++) {
                int i = i4 * 4 + c;
                const ulonglong2* wp =
                    reinterpret_cast<const ulonglong2*>(&Wt[i * DIM + jg]);
                ulonglong2 w0 = wp[0], w1 = wp[1];   // 8 cols (broadcast)
                unsigned long long s0, s1;
                asm("mov.b64 %0, {%1, %1};" : "=l"(s0) : "f"(a[0][c]));
                asm("mov.b64 %0, {%1, %1};" : "=l"(s1) : "f"(a[1][c]));
                asm("fma.rn.f32x2 %0, %1, %2, %0;" : "+l"(acc[0][0]) : "l"(s0), "l"(w0.x));
                asm("fma.rn.f32x2 %0, %1, %2, %0;" : "+l"(acc[0][1]) : "l"(s0), "l"(w0.y));
                asm("fma.rn.f32x2 %0, %1, %2, %0;" : "+l"(acc[0][2]) : "l"(s0), "l"(w1.x));
                asm("fma.rn.f32x2 %0, %1, %2, %0;" : "+l"(acc[0][3]) : "l"(s0), "l"(w1.y));
                asm("fma.rn.f32x2 %0, %1, %2, %0;" : "+l"(acc[1][0]) : "l"(s1), "l"(w0.x));
                asm("fma.rn.f32x2 %0, %1, %2, %0;" : "+l"(acc[1][1]) : "l"(s1), "l"(w0.y));
                asm("fma.rn.f32x2 %0, %1, %2, %0;" : "+l"(acc[1][2]) : "l"(s1), "l"(w1.x));
                asm("fma.rn.f32x2 %0, %1, %2, %0;" : "+l"(acc[1][3]) : "l"(s1), "l"(w1.y));
            }
        }

        // ---- store y16: 8 cols = 16B per node ----
#pragma unroll
        for (int q = 0; q < 2; q++) {
            int node = tbase + lane + 32 * q;
            if (node >= n) continue;
            float r[8];
            asm("mov.b64 {%0, %1}, %2;" : "=f"(r[0]), "=f"(r[1]) : "l"(acc[q][0]));
            asm("mov.b64 {%0, %1}, %2;" : "=f"(r[2]), "=f"(r[3]) : "l"(acc[q][1]));
            asm("mov.b64 {%0, %1}, %2;" : "=f"(r[4]), "=f"(r[5]) : "l"(acc[q][2]));
            asm("mov.b64 {%0, %1}, %2;" : "=f"(r[6]), "=f"(r[7]) : "l"(acc[q][3]));
            uint4 p;
            __half2 h;
            h = __floats2half2_rn(r[0], r[1]); p.x = *reinterpret_cast<uint32_t*>(&h);
            h = __floats2half2_rn(r[2], r[3]); p.y = *reinterpret_cast<uint32_t*>(&h);
            h = __floats2half2_rn(r[4], r[5]); p.z = *reinterpret_cast<uint32_t*>(&h);
            h = __floats2half2_rn(r[6], r[7]); p.w = *reinterpret_cast<uint32_t*>(&h);
            *reinterpret_cast<uint4*>(g_y16 + (size_t)node * DIM + jg) = p;
        }
    }

    grid_barrier(G);

    // ================= Phase B1: raw tile sums (tiles of 1024) =============
    int nst = (n + 1023) >> 10;
    for (int t = bid; t < nst; t += (int)G) {
        int base = t * 1024 + tid * 4;
        int s = 0;
        if (base + 3 < n) {
            int4 v = *reinterpret_cast<const int4*>(g_count + base);
            s = v.x + v.y + v.z + v.w;
        } else {
            for (int j = 0; j < 4 && base + j < n; j++) s += g_count[base + j];
        }
#pragma unroll
        for (int d = 16; d > 0; d >>= 1)
            s += __shfl_xor_sync(0xffffffffu, s, d);
        if (lane == 0) s_warp[wid] = s;
        __syncthreads();
        if (tid == 0) {
            int tot = 0;
#pragma unroll
            for (int j = 0; j < 8; j++) tot += s_warp[j];
            g_tilesums[t] = tot;
        }
        __syncthreads();
    }

    grid_barrier(G);

    // ===== Phase B2: every block scans tile sums (redundant) + own tiles ====
    {
        int v0 = 0;
        if (tid < MAX_TILES) {
            v0 = (tid < nst) ? g_tilesums[tid] : 0;
            s_sums[tid] = v0;
        }
        __syncthreads();
#pragma unroll
        for (int d = 1; d < MAX_TILES; d <<= 1) {
            int t = (tid < MAX_TILES && tid >= d) ? s_sums[tid - d] : 0;
            __syncthreads();
            if (tid < MAX_TILES) s_sums[tid] += t;
            __syncthreads();
        }
        if (tid < MAX_TILES) s_sums[tid] -= v0;   // exclusive
        __syncthreads();
    }
    for (int t = bid; t < nst; t += (int)G) {
        int tile_base = s_sums[t];
        int base = t * 1024 + tid * 4;
        int4 v = make_int4(0, 0, 0, 0);
        if (base + 3 < n) {
            v = *reinterpret_cast<const int4*>(g_count + base);
        } else {
            if (base + 0 < n) v.x = g_count[base + 0];
            if (base + 1 < n) v.y = g_count[base + 1];
            if (base + 2 < n) v.z = g_count[base + 2];
            if (base + 3 < n) v.w = g_count[base + 3];
        }
        int s1 = v.x + v.y, s2 = s1 + v.z, s3 = s2 + v.w;
        int tsum = s3;
        int p = tsum;
#pragma unroll
        for (int d = 1; d < 32; d <<= 1) {
            int t2 = __shfl_up_sync(0xffffffffu, p, d);
            if (lane >= d) p += t2;
        }
        if (lane == 31) s_warp[wid] = p;
        __syncthreads();
        if (wid == 0 && lane < 8) {
            int w = s_warp[lane];
            int q = w;
#pragma unroll
            for (int d = 1; d < 8; d <<= 1) {
                int t2 = __shfl_up_sync(0xffu, q, d);
                if (lane >= d) q += t2;
            }
            s_warp[lane] = q - w;
        }
        __syncthreads();
        int excl = tile_base + s_warp[wid] + (p - tsum);
        if (base + 0 < n) g_offset[base + 0] = excl;
        if (base + 1 < n) g_offset[base + 1] = excl + v.x;
        if (base + 2 < n) g_offset[base + 2] = excl + s1;
        if (base + 3 < n) g_offset[base + 3] = excl + s2;
        __syncthreads();
    }

    grid_barrier(G);

    // ================= Phase C: fill (absolute cursors) =====================
    int nq = (e + 3) >> 2;
    for (int q = bid * 256 + tid; q < nq; q += (int)G * 256) {
        int i = q * 4;
        if (i + 4 <= e) {
            int4 d4 = __ldg(reinterpret_cast<const int4*>(dst + i));
            int4 s4 = __ldg(reinterpret_cast<const int4*>(src + i));
            int p0 = atomicAdd(&g_offset[d4.x], 1);
            int p1 = atomicAdd(&g_offset[d4.y], 1);
            int p2 = atomicAdd(&g_offset[d4.z], 1);
            int p3 = atomicAdd(&g_offset[d4.w], 1);
            g_sorted_src[p0] = s4.x;
            g_sorted_src[p1] = s4.y;
            g_sorted_src[p2] = s4.z;
            g_sorted_src[p3] = s4.w;
        } else {
            for (; i < e; i++) {
                int d = __ldg(dst + i);
                int p = atomicAdd(&g_offset[d], 1);
                g_sorted_src[p] = __ldg(src + i);
            }
        }
    }

    grid_barrier(G);

    // ================= Phase D: gather + epilogue ===========================
    // After fill, g_offset[node] == absolute END of node's edge range.
    int half = lane >> 4;
    int c16  = lane & 15;
    const uint2* __restrict__ y2 = reinterpret_cast<const uint2*>(g_y16);
    for (int node = bid * 8 + wid; node < n; node += (int)G * 8) {
        int deg = __ldg(g_count + node);
        int end = __ldg(g_offset + node);
        int k   = end - deg;

        float4 acc0 = make_float4(0.f, 0.f, 0.f, 0.f);
        float4 acc1 = make_float4(0.f, 0.f, 0.f, 0.f);

        for (; k + 8 <= end; k += 8) {
            int s0 = __ldg(g_sorted_src + k + 0 + half);
            int s1 = __ldg(g_sorted_src + k + 2 + half);
            int s2 = __ldg(g_sorted_src + k + 4 + half);
            int s3 = __ldg(g_sorted_src + k + 6 + half);
            uint2 v0 = __ldg(y2 + (size_t)s0 * 16 + c16);
            uint2 v1 = __ldg(y2 + (size_t)s1 * 16 + c16);
            uint2 v2 = __ldg(y2 + (size_t)s2 * 16 + c16);
            uint2 v3 = __ldg(y2 + (size_t)s3 * 16 + c16);
            acc_h16(acc0, h2add(h2add(v0, v1), h2add(v2, v3)));
        }
        if (k + 4 <= end) {
            int s0 = __ldg(g_sorted_src + k + 0 + half);
            int s1 = __ldg(g_sorted_src + k + 2 + half);
            uint2 v0 = __ldg(y2 + (size_t)s0 * 16 + c16);
            uint2 v1 = __ldg(y2 + (size_t)s1 * 16 + c16);
            acc_h16(acc1, h2add(v0, v1));
            k += 4;
        }
        if (k + 2 <= end) {
            int s = __ldg(g_sorted_src + k + half);
            uint2 v = __ldg(y2 + (size_t)s * 16 + c16);
            acc_h16(acc0, v);
            k += 2;
        }
        if (k < end && half == 0) {
            int s = __ldg(g_sorted_src + k);
            uint2 v = __ldg(y2 + (size_t)s * 16 + c16);
            acc_h16(acc1, v);
        }

        acc0.x += acc1.x; acc0.y += acc1.y; acc0.z += acc1.z; acc0.w += acc1.w;

        acc0.x += __shfl_xor_sync(0xffffffffu, acc0.x, 16);
        acc0.y += __shfl_xor_sync(0xffffffffu, acc0.y, 16);
        acc0.z += __shfl_xor_sync(0xffffffffu, acc0.z, 16);
        acc0.w += __shfl_xor_sync(0xffffffffu, acc0.w, 16);

        if (half == 0) {
            float nv = __ldg(norm + node);
            float4 bv = reinterpret_cast<const float4*>(bias)[c16];
            acc0.x = fmaf(acc0.x, nv, bv.x);
            acc0.y = fmaf(acc0.y, nv, bv.y);
            acc0.z = fmaf(acc0.z, nv, bv.z);
            acc0.w = fmaf(acc0.w, nv, bv.w);
            reinterpret_cast<float4*>(out + (size_t)node * DIM)[c16] = acc0;
        }
    }
}

// ---------------------------------------------------------------------------
// Launch. Inputs: 0 feature [N,64] f32, 1 norm [N] f32, 2 src [E] i32,
//                 3 dst [E] i32, 4 W [64,64] f32, 5 b [64] f32. out [N,64] f32.
// ---------------------------------------------------------------------------
extern "C" void kernel_launch(void* const* d_in, const int* in_sizes, int n_in,
                              void* d_out, int out_size) {
    const float* feature = (const float*)d_in[0];
    const float* norm    = (const float*)d_in[1];
    const int*   src     = (const int*)d_in[2];
    const int*   dst     = (const int*)d_in[3];
    const float* W       = (const float*)d_in[4];
    const float* b       = (const float*)d_in[5];
    float*       out     = (float*)d_out;

    int n = in_sizes[1];
    int e = in_sizes[2];

    void* count_ptr = nullptr;
    cudaGetSymbolAddress(&count_ptr, g_count);
    cudaMemsetAsync(count_ptr, 0, (size_t)n * sizeof(int));

    // Grid sized for guaranteed co-residency (software grid barrier safety).
    int dev = 0, sms = 148, maxb = 0;
    cudaGetDevice(&dev);
    cudaDeviceGetAttribute(&sms, cudaDevAttrMultiProcessorCount, dev);
    cudaOccupancyMaxActiveBlocksPerMultiprocessor(&maxb, fused_kernel, 256, 0);
    if (maxb < 1) maxb = 1;
    unsigned G = (unsigned)(sms * maxb);

    fused_kernel<<<G, 256>>>(feature, norm, W, src, dst, b, out, n, e, G);
}